// round 7
// baseline (speedup 1.0000x reference)
#include <cuda_runtime.h>
#include <cuda_bf16.h>
#include <stdint.h>

#define D 128
#define NMAX 100000
#define EMAX 1600000
#define NGRAPH 512
#define NLAYER 4
#define LN_EPS 1e-5f

#define SCAN_TPB 256
#define SCAN_ITEMS 8
#define SCAN_BLOCK (SCAN_TPB * SCAN_ITEMS)   // 2048
#define SCAN_MAXBLOCKS 1024

// ---------------- scratch (no allocs allowed) ----------------
__device__ __nv_bfloat16 d_bufG[(size_t)NMAX * D];   // g = (in @ W) * dinv[row], bf16
__device__ float d_bufA[(size_t)NMAX * D];
__device__ float d_bufB[(size_t)NMAX * D];
__device__ __nv_bfloat16 d_Whi[NLAYER * D * D];
__device__ __nv_bfloat16 d_Wlo[NLAYER * D * D];
__device__ float d_dinv[NMAX];
__device__ int   d_src[EMAX];
__device__ int   d_dst[EMAX];
__device__ int   d_csr_src[EMAX];
__device__ int   d_cnt_int[NMAX];
__device__ int   d_row_start[NMAX + 1];
__device__ int   d_wr_ptr[NMAX];
__device__ int   d_blockSums[SCAN_MAXBLOCKS];
__device__ int   d_batch32[NMAX];
__device__ float d_pooled[NGRAPH * D];
__device__ float d_gcnt[NGRAPH];
__device__ int   d_is64;

// ---------------- dtype detection: int64 vs int32 indices ----------------
__global__ void detect_kernel(const int* __restrict__ w) {
    if (threadIdx.x == 0 && blockIdx.x == 0) {
        int zeros = 0;
        #pragma unroll
        for (int k = 0; k < 64; k++)
            if (w[2 * k + 1] == 0) zeros++;
        d_is64 = (zeros == 64) ? 1 : 0;
    }
}

// ---------------- W hi/lo split (once for all layers) ----------------
__global__ void wsplit_kernel(const float* __restrict__ Ws,
                              __nv_bfloat16* __restrict__ Whi,
                              __nv_bfloat16* __restrict__ Wlo) {
    int i = blockIdx.x * blockDim.x + threadIdx.x;   // 0 .. NLAYER*D*D-1
    if (i >= NLAYER * D * D) return;
    float w = Ws[i];
    __nv_bfloat16 h = __float2bfloat16(w);
    Whi[i] = h;
    Wlo[i] = __float2bfloat16(w - __bfloat162float(h));
}

// ---------------- fused: convert edges + degree histogram ----------------
__global__ void cvt_hist_kernel(const void* __restrict__ ei,
                                int* __restrict__ src, int* __restrict__ dst,
                                int* __restrict__ cnt, int E, int n) {
    int i = blockIdx.x * blockDim.x + threadIdx.x;
    if (i >= E) return;
    int s, d2;
    if (d_is64) {
        const long long* p = (const long long*)ei;
        s  = (int)p[i];
        d2 = (int)p[(size_t)E + i];
    } else {
        const int* p = (const int*)ei;
        s  = p[i];
        d2 = p[E + i];
    }
    s  = min(max(s, 0), n - 1);
    d2 = min(max(d2, 0), n - 1);
    src[i] = s;
    dst[i] = d2;
    atomicAdd(&cnt[d2], 1);
}

// ---------------- fused: convert batch + graph counts ----------------
__global__ void cvt_batch_kernel(const void* __restrict__ b,
                                 int* __restrict__ outb,
                                 float* __restrict__ gcnt, int n) {
    int i = blockIdx.x * blockDim.x + threadIdx.x;
    if (i >= n) return;
    int v;
    if (d_is64) v = (int)((const long long*)b)[i];
    else        v = ((const int*)b)[i];
    v = min(max(v, 0), NGRAPH - 1);
    outb[i] = v;
    atomicAdd(&gcnt[v], 1.0f);
}

// ---------------- exclusive scan (3 kernels) ----------------
__global__ void scanA_kernel(const int* __restrict__ cnt, int* __restrict__ row_start,
                             int* __restrict__ blockSums, int n) {
    __shared__ int ssum[SCAN_TPB];
    int b = blockIdx.x, t = threadIdx.x;
    int base = b * SCAN_BLOCK + t * SCAN_ITEMS;
    int v[SCAN_ITEMS];
    int s = 0;
    #pragma unroll
    for (int i = 0; i < SCAN_ITEMS; i++) {
        v[i] = (base + i < n) ? cnt[base + i] : 0;
        s += v[i];
    }
    ssum[t] = s;
    __syncthreads();
    for (int off = 1; off < SCAN_TPB; off <<= 1) {
        int x = (t >= off) ? ssum[t - off] : 0;
        __syncthreads();
        ssum[t] += x;
        __syncthreads();
    }
    int run = ssum[t] - s;
    #pragma unroll
    for (int i = 0; i < SCAN_ITEMS; i++) {
        if (base + i < n) row_start[base + i] = run;
        run += v[i];
    }
    if (t == SCAN_TPB - 1) blockSums[b] = ssum[t];
}

__global__ void scanB_kernel(int* __restrict__ blockSums, int nb) {
    __shared__ int ssum[SCAN_MAXBLOCKS];
    int t = threadIdx.x;
    int v = (t < nb) ? blockSums[t] : 0;
    ssum[t] = v;
    __syncthreads();
    for (int off = 1; off < SCAN_MAXBLOCKS; off <<= 1) {
        int x = (t >= off) ? ssum[t - off] : 0;
        __syncthreads();
        ssum[t] += x;
        __syncthreads();
    }
    if (t < nb) blockSums[t] = ssum[t] - v;
}

__global__ void scanC_kernel(int* __restrict__ row_start, const int* __restrict__ blockSums,
                             int* __restrict__ wr_ptr, const int* __restrict__ cnt,
                             float* __restrict__ dinv, int n, int E) {
    int i = blockIdx.x * blockDim.x + threadIdx.x;
    if (i < n) {
        int v = row_start[i] + blockSums[i / SCAN_BLOCK];
        row_start[i] = v;
        wr_ptr[i] = v;
        dinv[i] = rsqrtf((float)cnt[i] + 1.0f);
    }
    if (i == 0) row_start[n] = E;
}

__global__ void scatter_kernel(const int* __restrict__ src, const int* __restrict__ dst,
                               int* __restrict__ wr_ptr, int* __restrict__ csr_src, int E) {
    int e = blockIdx.x * blockDim.x + threadIdx.x;
    if (e < E) {
        int p = atomicAdd(&wr_ptr[dst[e]], 1);
        csr_src[p] = src[e];
    }
}

// ---------------- tensor-core GEMM: g = bf16((in @ W) * dinv[row]) ----------------
#define WPAD 136

__device__ __forceinline__ void ldsm_x4(uint32_t* r, uint32_t addr) {
    asm volatile("ldmatrix.sync.aligned.m8n8.x4.shared.b16 {%0,%1,%2,%3}, [%4];"
                 : "=r"(r[0]), "=r"(r[1]), "=r"(r[2]), "=r"(r[3]) : "r"(addr));
}
__device__ __forceinline__ void ldsm_x4t(uint32_t* r, uint32_t addr) {
    asm volatile("ldmatrix.sync.aligned.m8n8.x4.trans.shared.b16 {%0,%1,%2,%3}, [%4];"
                 : "=r"(r[0]), "=r"(r[1]), "=r"(r[2]), "=r"(r[3]) : "r"(addr));
}
__device__ __forceinline__ void mma_bf16(float* c, const uint32_t* a, const uint32_t* b) {
    asm volatile("mma.sync.aligned.m16n8k16.row.col.f32.bf16.bf16.f32 "
                 "{%0,%1,%2,%3}, {%4,%5,%6,%7}, {%8,%9}, {%0,%1,%2,%3};"
                 : "+f"(c[0]), "+f"(c[1]), "+f"(c[2]), "+f"(c[3])
                 : "r"(a[0]), "r"(a[1]), "r"(a[2]), "r"(a[3]), "r"(b[0]), "r"(b[1]));
}

__global__ void __launch_bounds__(256, 2)
gemm_kernel(const float* __restrict__ in,
            const __nv_bfloat16* __restrict__ WhiG,
            const __nv_bfloat16* __restrict__ WloG,
            const float* __restrict__ dinv, __nv_bfloat16* __restrict__ out, int n) {
    extern __shared__ __nv_bfloat16 sm[];
    __nv_bfloat16* Wh = sm;
    __nv_bfloat16* Wl = Wh + 128 * WPAD;
    __nv_bfloat16* Xh = Wl + 128 * WPAD;
    __nv_bfloat16* Xl = Xh + 64 * WPAD;

    int tid  = threadIdx.x;
    int row0 = blockIdx.x * 64;

    // stage W (pre-split): 2048 uint4 per matrix, straight copies
    {
        const uint4* src_h = (const uint4*)WhiG;
        const uint4* src_l = (const uint4*)WloG;
        #pragma unroll
        for (int i = tid; i < 2048; i += 256) {
            int r = i >> 4;            // 16 uint4 per 128-elem row
            int c = (i & 15) * 8;      // element offset
            *(uint4*)(Wh + r * WPAD + c) = src_h[i];
            *(uint4*)(Wl + r * WPAD + c) = src_l[i];
        }
    }
    // stage X tile with hi/lo conversion (no redundancy: each row once per layer)
    #pragma unroll
    for (int i = tid; i < 64 * 32; i += 256) {
        int r = i >> 5, c = (i & 31) * 4;
        float4 v = make_float4(0.f, 0.f, 0.f, 0.f);
        if (row0 + r < n)
            v = *(const float4*)(in + (size_t)(row0 + r) * D + c);
        __nv_bfloat16 h0 = __float2bfloat16(v.x);
        __nv_bfloat16 h1 = __float2bfloat16(v.y);
        __nv_bfloat16 h2 = __float2bfloat16(v.z);
        __nv_bfloat16 h3 = __float2bfloat16(v.w);
        __nv_bfloat16* ph = Xh + r * WPAD + c;
        __nv_bfloat16* pl = Xl + r * WPAD + c;
        ph[0] = h0; ph[1] = h1; ph[2] = h2; ph[3] = h3;
        pl[0] = __float2bfloat16(v.x - __bfloat162float(h0));
        pl[1] = __float2bfloat16(v.y - __bfloat162float(h1));
        pl[2] = __float2bfloat16(v.z - __bfloat162float(h2));
        pl[3] = __float2bfloat16(v.w - __bfloat162float(h3));
    }
    __syncthreads();

    int wid  = tid >> 5;
    int lane = tid & 31;
    int wm = wid >> 2;
    int wn = wid & 3;

    int l7  = lane & 7;
    int lb3 = (lane >> 3) & 1;
    int lb4 = (lane >> 4) & 1;

    float acc[2][4][4];
    #pragma unroll
    for (int mt = 0; mt < 2; mt++)
        #pragma unroll
        for (int nt = 0; nt < 4; nt++)
            #pragma unroll
            for (int q = 0; q < 4; q++) acc[mt][nt][q] = 0.f;

    #pragma unroll
    for (int kk = 0; kk < 8; kk++) {
        int k0 = kk * 16;
        uint32_t ah[2][4], al[2][4];
        #pragma unroll
        for (int mt = 0; mt < 2; mt++) {
            int r = wm * 32 + mt * 16 + l7 + lb3 * 8;
            int c = k0 + lb4 * 8;
            ldsm_x4(ah[mt], (uint32_t)__cvta_generic_to_shared(Xh + r * WPAD + c));
            ldsm_x4(al[mt], (uint32_t)__cvta_generic_to_shared(Xl + r * WPAD + c));
        }
        uint32_t bh[4][2], bl[4][2];
        #pragma unroll
        for (int p = 0; p < 2; p++) {
            int r = k0 + l7 + lb3 * 8;
            int c = wn * 32 + p * 16 + lb4 * 8;
            uint32_t t[4];
            ldsm_x4t(t, (uint32_t)__cvta_generic_to_shared(Wh + r * WPAD + c));
            bh[2*p][0] = t[0]; bh[2*p][1] = t[1]; bh[2*p+1][0] = t[2]; bh[2*p+1][1] = t[3];
            ldsm_x4t(t, (uint32_t)__cvta_generic_to_shared(Wl + r * WPAD + c));
            bl[2*p][0] = t[0]; bl[2*p][1] = t[1]; bl[2*p+1][0] = t[2]; bl[2*p+1][1] = t[3];
        }
        #pragma unroll
        for (int mt = 0; mt < 2; mt++)
            #pragma unroll
            for (int nt = 0; nt < 4; nt++) {
                mma_bf16(acc[mt][nt], ah[mt], bh[nt]);
                mma_bf16(acc[mt][nt], ah[mt], bl[nt]);
                mma_bf16(acc[mt][nt], al[mt], bh[nt]);
            }
    }

    int quad = lane >> 2;
    int tcol = (lane & 3) * 2;
    #pragma unroll
    for (int mt = 0; mt < 2; mt++) {
        int r_lo = row0 + wm * 32 + mt * 16 + quad;
        int r_hi = r_lo + 8;
        float s_lo = (r_lo < n) ? dinv[r_lo] : 0.f;
        float s_hi = (r_hi < n) ? dinv[r_hi] : 0.f;
        #pragma unroll
        for (int nt = 0; nt < 4; nt++) {
            int c = wn * 32 + nt * 8 + tcol;
            if (r_lo < n) {
                __nv_bfloat162 p = __floats2bfloat162_rn(acc[mt][nt][0] * s_lo,
                                                         acc[mt][nt][1] * s_lo);
                *(uint32_t*)(out + (size_t)r_lo * D + c) = *(uint32_t*)&p;
            }
            if (r_hi < n) {
                __nv_bfloat162 p = __floats2bfloat162_rn(acc[mt][nt][2] * s_hi,
                                                         acc[mt][nt][3] * s_hi);
                *(uint32_t*)(out + (size_t)r_hi * D + c) = *(uint32_t*)&p;
            }
        }
    }
}

// ---------------- fused CSR aggregate + post ----------------
// warp per dst row; half-warp per edge; up to 8 uint4 loads in flight per lane.
__device__ __forceinline__ void acc_bf16x8(float* a, uint4 q) {
    __nv_bfloat162 b0 = *(__nv_bfloat162*)&q.x;
    __nv_bfloat162 b1 = *(__nv_bfloat162*)&q.y;
    __nv_bfloat162 b2 = *(__nv_bfloat162*)&q.z;
    __nv_bfloat162 b3 = *(__nv_bfloat162*)&q.w;
    float2 f0 = __bfloat1622float2(b0);
    float2 f1 = __bfloat1622float2(b1);
    float2 f2 = __bfloat1622float2(b2);
    float2 f3 = __bfloat1622float2(b3);
    a[0] += f0.x; a[1] += f0.y; a[2] += f1.x; a[3] += f1.y;
    a[4] += f2.x; a[5] += f2.y; a[6] += f3.x; a[7] += f3.y;
}

__global__ void __launch_bounds__(256)
agg_post_kernel(const __nv_bfloat16* __restrict__ g,
                const int* __restrict__ csr_src, const int* __restrict__ row_start,
                const float* __restrict__ resid,
                const float* __restrict__ dinv,
                const float* __restrict__ bias,
                const float* __restrict__ gamma,
                const float* __restrict__ beta,
                float* __restrict__ h_out,
                const int* __restrict__ batch,
                float* __restrict__ pooled,
                int n, int do_relu, int do_pool) {
    int warp = (blockIdx.x * blockDim.x + threadIdx.x) >> 5;
    int lane = threadIdx.x & 31;
    if (warp >= n) return;

    int half = lane >> 4;
    int hl   = lane & 15;
    int colb = hl * 8;

    int beg = row_start[warp];
    int cnt = row_start[warp + 1] - beg;

    float acc[8];
    #pragma unroll
    for (int k = 0; k < 8; k++) acc[k] = 0.f;

    if (half == 0) {   // self-loop term
        uint4 q = *(const uint4*)(g + (size_t)warp * D + colb);
        acc_bf16x8(acc, q);
    }

    for (int base = 0; base < cnt; base += 32) {
        int m = min(32, cnt - base);
        int idx = (base + lane < cnt) ? __ldg(&csr_src[beg + base + lane]) : 0;
        int j = 0;
        // 8 pairs = 16 edges per iteration (8 loads in flight per lane)
        for (; j + 16 <= m; j += 16) {
            uint4 v[8];
            #pragma unroll
            for (int p = 0; p < 8; p++) {
                int s = __shfl_sync(0xffffffffu, idx, j + 2 * p + half);
                v[p] = *(const uint4*)(g + (size_t)s * D + colb);
            }
            #pragma unroll
            for (int p = 0; p < 8; p++) acc_bf16x8(acc, v[p]);
        }
        for (; j + 8 <= m; j += 8) {
            uint4 v[4];
            #pragma unroll
            for (int p = 0; p < 4; p++) {
                int s = __shfl_sync(0xffffffffu, idx, j + 2 * p + half);
                v[p] = *(const uint4*)(g + (size_t)s * D + colb);
            }
            #pragma unroll
            for (int p = 0; p < 4; p++) acc_bf16x8(acc, v[p]);
        }
        for (; j + 2 <= m; j += 2) {
            int s = __shfl_sync(0xffffffffu, idx, j + half);
            uint4 v = *(const uint4*)(g + (size_t)s * D + colb);
            acc_bf16x8(acc, v);
        }
        if (j < m) {   // odd tail: half 0 takes it
            int s = __shfl_sync(0xffffffffu, idx, j);
            if (half == 0) {
                uint4 v = *(const uint4*)(g + (size_t)s * D + colb);
                acc_bf16x8(acc, v);
            }
        }
    }

    #pragma unroll
    for (int k = 0; k < 8; k++)
        acc[k] += __shfl_xor_sync(0xffffffffu, acc[k], 16);

    float sc = dinv[warp];
    float t[8];
    {
        float4 b0 = *(const float4*)(bias + colb);
        float4 b1 = *(const float4*)(bias + colb + 4);
        t[0] = acc[0] * sc + b0.x; t[1] = acc[1] * sc + b0.y;
        t[2] = acc[2] * sc + b0.z; t[3] = acc[3] * sc + b0.w;
        t[4] = acc[4] * sc + b1.x; t[5] = acc[5] * sc + b1.y;
        t[6] = acc[6] * sc + b1.z; t[7] = acc[7] * sc + b1.w;
    }

    float sum = 0.f;
    #pragma unroll
    for (int k = 0; k < 8; k++) sum += t[k];
    #pragma unroll
    for (int o = 16; o > 0; o >>= 1) sum += __shfl_xor_sync(0xffffffffu, sum, o);
    float mu = sum * (1.0f / (2 * D));

    float ss = 0.f;
    #pragma unroll
    for (int k = 0; k < 8; k++) { t[k] -= mu; ss += t[k] * t[k]; }
    #pragma unroll
    for (int o = 16; o > 0; o >>= 1) ss += __shfl_xor_sync(0xffffffffu, ss, o);
    float inv = rsqrtf(ss * (1.0f / (2 * D)) + LN_EPS);

    float y[8];
    {
        float4 g0 = *(const float4*)(gamma + colb);
        float4 g1 = *(const float4*)(gamma + colb + 4);
        float4 e0 = *(const float4*)(beta + colb);
        float4 e1 = *(const float4*)(beta + colb + 4);
        y[0] = t[0] * inv * g0.x + e0.x; y[1] = t[1] * inv * g0.y + e0.y;
        y[2] = t[2] * inv * g0.z + e0.z; y[3] = t[3] * inv * g0.w + e0.w;
        y[4] = t[4] * inv * g1.x + e1.x; y[5] = t[5] * inv * g1.y + e1.y;
        y[6] = t[6] * inv * g1.z + e1.z; y[7] = t[7] * inv * g1.w + e1.w;
    }

    if (resid) {
        float4 r0 = *(const float4*)(resid + (size_t)warp * D + colb);
        float4 r1 = *(const float4*)(resid + (size_t)warp * D + colb + 4);
        y[0] += r0.x; y[1] += r0.y; y[2] += r0.z; y[3] += r0.w;
        y[4] += r1.x; y[5] += r1.y; y[6] += r1.z; y[7] += r1.w;
    }
    if (do_relu) {
        #pragma unroll
        for (int k = 0; k < 8; k++) y[k] = fmaxf(y[k], 0.f);
    }

    if (half == 0) {
        if (do_pool) {
            int b = batch[warp];
            float* p = pooled + (size_t)b * D + colb;
            asm volatile("red.global.add.v4.f32 [%0], {%1,%2,%3,%4};"
                         :: "l"(p), "f"(y[0]), "f"(y[1]), "f"(y[2]), "f"(y[3]) : "memory");
            asm volatile("red.global.add.v4.f32 [%0], {%1,%2,%3,%4};"
                         :: "l"(p + 4), "f"(y[4]), "f"(y[5]), "f"(y[6]), "f"(y[7]) : "memory");
        } else {
            float* p = h_out + (size_t)warp * D + colb;
            *(float4*)p       = make_float4(y[0], y[1], y[2], y[3]);
            *(float4*)(p + 4) = make_float4(y[4], y[5], y[6], y[7]);
        }
    }
}

// ---------------- final readout ----------------
__global__ void out_kernel(const float* __restrict__ pooled, const float* __restrict__ gcnt,
                           const float* __restrict__ lin_w, const float* __restrict__ lin_b,
                           float* __restrict__ out, int ngraphs) {
    int warp = (blockIdx.x * blockDim.x + threadIdx.x) >> 5;
    int lane = threadIdx.x & 31;
    if (warp >= ngraphs) return;
    float acc = 0.f;
    #pragma unroll
    for (int q = 0; q < 4; q++) {
        int j = lane + 32 * q;
        acc += pooled[(size_t)warp * D + j] * lin_w[j];
    }
    #pragma unroll
    for (int o = 16; o > 0; o >>= 1) acc += __shfl_xor_sync(0xffffffffu, acc, o);
    if (lane == 0)
        out[warp] = acc / fmaxf(gcnt[warp], 1.0f) + lin_b[0];
}

// ---------------- host launcher ----------------
extern "C" void kernel_launch(void* const* d_in, const int* in_sizes, int n_in,
                              void* d_out, int out_size) {
    const float* x      = (const float*)d_in[0];
    const void*  ei     = d_in[1];
    const void*  batch  = d_in[2];
    const float* Ws     = (const float*)d_in[3];
    const float* bs     = (const float*)d_in[4];
    const float* gammas = (const float*)d_in[5];
    const float* betas  = (const float*)d_in[6];
    const float* lin_w  = (const float*)d_in[7];
    const float* lin_b  = (const float*)d_in[8];
    float* out = (float*)d_out;

    int n = in_sizes[2];
    int E = in_sizes[1] / 2;
    int ngraphs = out_size;
    if (n > NMAX) n = NMAX;
    if (E > EMAX) E = EMAX;

    __nv_bfloat16 *bufG, *Whi, *Wlo;
    float *bufA, *bufB, *dinv, *pooled, *gcnt;
    int *src, *dst, *csr_src, *cnt_int, *row_start, *wr_ptr, *blockSums, *batch32;
    cudaGetSymbolAddress((void**)&bufG,      d_bufG);
    cudaGetSymbolAddress((void**)&Whi,       d_Whi);
    cudaGetSymbolAddress((void**)&Wlo,       d_Wlo);
    cudaGetSymbolAddress((void**)&bufA,      d_bufA);
    cudaGetSymbolAddress((void**)&bufB,      d_bufB);
    cudaGetSymbolAddress((void**)&dinv,      d_dinv);
    cudaGetSymbolAddress((void**)&src,       d_src);
    cudaGetSymbolAddress((void**)&dst,       d_dst);
    cudaGetSymbolAddress((void**)&csr_src,   d_csr_src);
    cudaGetSymbolAddress((void**)&cnt_int,   d_cnt_int);
    cudaGetSymbolAddress((void**)&row_start, d_row_start);
    cudaGetSymbolAddress((void**)&wr_ptr,    d_wr_ptr);
    cudaGetSymbolAddress((void**)&blockSums, d_blockSums);
    cudaGetSymbolAddress((void**)&batch32,   d_batch32);
    cudaGetSymbolAddress((void**)&pooled,    d_pooled);
    cudaGetSymbolAddress((void**)&gcnt,      d_gcnt);

    const int smem_bytes = (2 * 128 * WPAD + 2 * 64 * WPAD) * sizeof(__nv_bfloat16);
    cudaFuncSetAttribute(gemm_kernel, cudaFuncAttributeMaxDynamicSharedMemorySize, smem_bytes);

    // ---- preamble ----
    detect_kernel<<<1, 32>>>((const int*)ei);
    cudaMemsetAsync(cnt_int, 0, (size_t)n * sizeof(int));
    cudaMemsetAsync(gcnt, 0, (size_t)ngraphs * sizeof(float));
    cudaMemsetAsync(pooled, 0, (size_t)ngraphs * D * sizeof(float));

    wsplit_kernel<<<(NLAYER * D * D + 255) / 256, 256>>>(Ws, Whi, Wlo);
    cvt_hist_kernel<<<(E + 255) / 256, 256>>>(ei, src, dst, cnt_int, E, n);
    cvt_batch_kernel<<<(n + 255) / 256, 256>>>(batch, batch32, gcnt, n);

    int nb = (n + SCAN_BLOCK - 1) / SCAN_BLOCK;
    scanA_kernel<<<nb, SCAN_TPB>>>(cnt_int, row_start, blockSums, n);
    scanB_kernel<<<1, SCAN_MAXBLOCKS>>>(blockSums, nb);
    scanC_kernel<<<(n + 255) / 256, 256>>>(row_start, blockSums, wr_ptr, cnt_int, dinv, n, E);
    scatter_kernel<<<(E + 255) / 256, 256>>>(src, dst, wr_ptr, csr_src, E);

    // ---- layers ----
    int gemm_blocks = (n + 63) / 64;
    int row_warp_blocks = (n + 7) / 8;
    const float* in_ptr = x;
    float* hbufs[2] = {bufA, bufB};
    for (int l = 0; l < 4; l++) {
        gemm_kernel<<<gemm_blocks, 256, smem_bytes>>>(in_ptr, Whi + (size_t)l * D * D,
                                                      Wlo + (size_t)l * D * D, dinv, bufG, n);
        float* h_out = hbufs[l & 1];
        int do_pool = (l == 3);
        agg_post_kernel<<<row_warp_blocks, 256>>>(bufG, csr_src, row_start,
                                                  (l == 0) ? nullptr : in_ptr,
                                                  dinv,
                                                  bs + l * D, gammas + l * D, betas + l * D,
                                                  h_out, batch32, pooled,
                                                  n, (l < 3) ? 1 : 0, do_pool);
        in_ptr = h_out;
    }

    out_kernel<<<(ngraphs * 32 + 255) / 256, 256>>>(pooled, gcnt, lin_w, lin_b, out, ngraphs);
}

// round 8
// speedup vs baseline: 1.0815x; 1.0815x over previous
#include <cuda_runtime.h>
#include <cuda_bf16.h>
#include <stdint.h>

#define D 128
#define NMAX 100000
#define EMAX 1600000
#define NGRAPH 512
#define NLAYER 4
#define LN_EPS 1e-5f

#define SCAN_TPB 256
#define SCAN_ITEMS 8
#define SCAN_BLOCK (SCAN_TPB * SCAN_ITEMS)   // 2048
#define SCAN_MAXBLOCKS 1024

// ---------------- scratch (no allocs allowed) ----------------
__device__ __nv_bfloat16 d_bufG[(size_t)NMAX * D];   // g = (in @ W) * dinv[row], bf16
__device__ float d_bufA[(size_t)NMAX * D];
__device__ float d_bufB[(size_t)NMAX * D];
__device__ __nv_bfloat16 d_Whi[NLAYER * D * D];
__device__ __nv_bfloat16 d_Wlo[NLAYER * D * D];
__device__ float d_dinv[NMAX];
__device__ int   d_src[EMAX];
__device__ int   d_dst[EMAX];
__device__ int   d_csr_src[EMAX];
__device__ int   d_cnt_int[NMAX];
__device__ int   d_row_start[NMAX + 1];
__device__ int   d_wr_ptr[NMAX];
__device__ int   d_blockSums[SCAN_MAXBLOCKS];
__device__ int   d_batch32[NMAX];
__device__ float d_pooled[NGRAPH * D];
__device__ float d_gcnt[NGRAPH];
__device__ int   d_is64;

// ---------------- dtype detection: int64 vs int32 indices ----------------
__global__ void detect_kernel(const int* __restrict__ w) {
    if (threadIdx.x == 0 && blockIdx.x == 0) {
        int zeros = 0;
        #pragma unroll
        for (int k = 0; k < 64; k++)
            if (w[2 * k + 1] == 0) zeros++;
        d_is64 = (zeros == 64) ? 1 : 0;
    }
}

// ---------------- W hi/lo split (once for all layers) ----------------
__global__ void wsplit_kernel(const float* __restrict__ Ws,
                              __nv_bfloat16* __restrict__ Whi,
                              __nv_bfloat16* __restrict__ Wlo) {
    int i = blockIdx.x * blockDim.x + threadIdx.x;
    if (i >= NLAYER * D * D) return;
    float w = Ws[i];
    __nv_bfloat16 h = __float2bfloat16(w);
    Whi[i] = h;
    Wlo[i] = __float2bfloat16(w - __bfloat162float(h));
}

// ---------------- fused: convert edges + degree histogram ----------------
__global__ void cvt_hist_kernel(const void* __restrict__ ei,
                                int* __restrict__ src, int* __restrict__ dst,
                                int* __restrict__ cnt, int E, int n) {
    int i = blockIdx.x * blockDim.x + threadIdx.x;
    if (i >= E) return;
    int s, d2;
    if (d_is64) {
        const long long* p = (const long long*)ei;
        s  = (int)p[i];
        d2 = (int)p[(size_t)E + i];
    } else {
        const int* p = (const int*)ei;
        s  = p[i];
        d2 = p[E + i];
    }
    s  = min(max(s, 0), n - 1);
    d2 = min(max(d2, 0), n - 1);
    src[i] = s;
    dst[i] = d2;
    atomicAdd(&cnt[d2], 1);
}

// ---------------- convert batch + graph counts (smem-aggregated) ----------------
__global__ void cvt_batch_kernel(const void* __restrict__ b,
                                 int* __restrict__ outb,
                                 float* __restrict__ gcnt, int n) {
    __shared__ int hist[NGRAPH];
    for (int k = threadIdx.x; k < NGRAPH; k += blockDim.x) hist[k] = 0;
    __syncthreads();
    int i = blockIdx.x * blockDim.x + threadIdx.x;
    if (i < n) {
        int v;
        if (d_is64) v = (int)((const long long*)b)[i];
        else        v = ((const int*)b)[i];
        v = min(max(v, 0), NGRAPH - 1);
        outb[i] = v;
        atomicAdd(&hist[v], 1);
    }
    __syncthreads();
    for (int k = threadIdx.x; k < NGRAPH; k += blockDim.x) {
        int c = hist[k];
        if (c) atomicAdd(&gcnt[k], (float)c);
    }
}

// ---------------- exclusive scan (3 kernels) ----------------
__global__ void scanA_kernel(const int* __restrict__ cnt, int* __restrict__ row_start,
                             int* __restrict__ blockSums, int n) {
    __shared__ int ssum[SCAN_TPB];
    int b = blockIdx.x, t = threadIdx.x;
    int base = b * SCAN_BLOCK + t * SCAN_ITEMS;
    int v[SCAN_ITEMS];
    int s = 0;
    #pragma unroll
    for (int i = 0; i < SCAN_ITEMS; i++) {
        v[i] = (base + i < n) ? cnt[base + i] : 0;
        s += v[i];
    }
    ssum[t] = s;
    __syncthreads();
    for (int off = 1; off < SCAN_TPB; off <<= 1) {
        int x = (t >= off) ? ssum[t - off] : 0;
        __syncthreads();
        ssum[t] += x;
        __syncthreads();
    }
    int run = ssum[t] - s;
    #pragma unroll
    for (int i = 0; i < SCAN_ITEMS; i++) {
        if (base + i < n) row_start[base + i] = run;
        run += v[i];
    }
    if (t == SCAN_TPB - 1) blockSums[b] = ssum[t];
}

__global__ void scanB_kernel(int* __restrict__ blockSums, int nb) {
    __shared__ int ssum[SCAN_MAXBLOCKS];
    int t = threadIdx.x;
    int v = (t < nb) ? blockSums[t] : 0;
    ssum[t] = v;
    __syncthreads();
    for (int off = 1; off < SCAN_MAXBLOCKS; off <<= 1) {
        int x = (t >= off) ? ssum[t - off] : 0;
        __syncthreads();
        ssum[t] += x;
        __syncthreads();
    }
    if (t < nb) blockSums[t] = ssum[t] - v;
}

__global__ void scanC_kernel(int* __restrict__ row_start, const int* __restrict__ blockSums,
                             int* __restrict__ wr_ptr, const int* __restrict__ cnt,
                             float* __restrict__ dinv, int n, int E) {
    int i = blockIdx.x * blockDim.x + threadIdx.x;
    if (i < n) {
        int v = row_start[i] + blockSums[i / SCAN_BLOCK];
        row_start[i] = v;
        wr_ptr[i] = v;
        dinv[i] = rsqrtf((float)cnt[i] + 1.0f);
    }
    if (i == 0) row_start[n] = E;
}

__global__ void scatter_kernel(const int* __restrict__ src, const int* __restrict__ dst,
                               int* __restrict__ wr_ptr, int* __restrict__ csr_src, int E) {
    int e = blockIdx.x * blockDim.x + threadIdx.x;
    if (e < E) {
        int p = atomicAdd(&wr_ptr[dst[e]], 1);
        csr_src[p] = src[e];
    }
}

// ---------------- tensor-core GEMM: g = bf16((in @ W) * dinv[row]) ----------------
#define WPAD 136

__device__ __forceinline__ void ldsm_x4(uint32_t* r, uint32_t addr) {
    asm volatile("ldmatrix.sync.aligned.m8n8.x4.shared.b16 {%0,%1,%2,%3}, [%4];"
                 : "=r"(r[0]), "=r"(r[1]), "=r"(r[2]), "=r"(r[3]) : "r"(addr));
}
__device__ __forceinline__ void ldsm_x4t(uint32_t* r, uint32_t addr) {
    asm volatile("ldmatrix.sync.aligned.m8n8.x4.trans.shared.b16 {%0,%1,%2,%3}, [%4];"
                 : "=r"(r[0]), "=r"(r[1]), "=r"(r[2]), "=r"(r[3]) : "r"(addr));
}
__device__ __forceinline__ void mma_bf16(float* c, const uint32_t* a, const uint32_t* b) {
    asm volatile("mma.sync.aligned.m16n8k16.row.col.f32.bf16.bf16.f32 "
                 "{%0,%1,%2,%3}, {%4,%5,%6,%7}, {%8,%9}, {%0,%1,%2,%3};"
                 : "+f"(c[0]), "+f"(c[1]), "+f"(c[2]), "+f"(c[3])
                 : "r"(a[0]), "r"(a[1]), "r"(a[2]), "r"(a[3]), "r"(b[0]), "r"(b[1]));
}

__global__ void __launch_bounds__(256, 2)
gemm_kernel(const float* __restrict__ in,
            const __nv_bfloat16* __restrict__ WhiG,
            const __nv_bfloat16* __restrict__ WloG,
            const float* __restrict__ dinv, __nv_bfloat16* __restrict__ out, int n) {
    extern __shared__ __nv_bfloat16 sm[];
    __nv_bfloat16* Wh = sm;
    __nv_bfloat16* Wl = Wh + 128 * WPAD;
    __nv_bfloat16* Xh = Wl + 128 * WPAD;
    __nv_bfloat16* Xl = Xh + 64 * WPAD;

    int tid  = threadIdx.x;
    int row0 = blockIdx.x * 64;

    // stage pre-split W: straight uint4 copies
    {
        const uint4* src_h = (const uint4*)WhiG;
        const uint4* src_l = (const uint4*)WloG;
        #pragma unroll
        for (int i = tid; i < 2048; i += 256) {
            int r = i >> 4;
            int c = (i & 15) * 8;
            *(uint4*)(Wh + r * WPAD + c) = src_h[i];
            *(uint4*)(Wl + r * WPAD + c) = src_l[i];
        }
    }
    // stage X tile with hi/lo conversion
    #pragma unroll
    for (int i = tid; i < 64 * 32; i += 256) {
        int r = i >> 5, c = (i & 31) * 4;
        float4 v = make_float4(0.f, 0.f, 0.f, 0.f);
        if (row0 + r < n)
            v = *(const float4*)(in + (size_t)(row0 + r) * D + c);
        __nv_bfloat16 h0 = __float2bfloat16(v.x);
        __nv_bfloat16 h1 = __float2bfloat16(v.y);
        __nv_bfloat16 h2 = __float2bfloat16(v.z);
        __nv_bfloat16 h3 = __float2bfloat16(v.w);
        __nv_bfloat16* ph = Xh + r * WPAD + c;
        __nv_bfloat16* pl = Xl + r * WPAD + c;
        ph[0] = h0; ph[1] = h1; ph[2] = h2; ph[3] = h3;
        pl[0] = __float2bfloat16(v.x - __bfloat162float(h0));
        pl[1] = __float2bfloat16(v.y - __bfloat162float(h1));
        pl[2] = __float2bfloat16(v.z - __bfloat162float(h2));
        pl[3] = __float2bfloat16(v.w - __bfloat162float(h3));
    }
    __syncthreads();

    int wid  = tid >> 5;
    int lane = tid & 31;
    int wm = wid >> 2;
    int wn = wid & 3;

    int l7  = lane & 7;
    int lb3 = (lane >> 3) & 1;
    int lb4 = (lane >> 4) & 1;

    float acc[2][4][4];
    #pragma unroll
    for (int mt = 0; mt < 2; mt++)
        #pragma unroll
        for (int nt = 0; nt < 4; nt++)
            #pragma unroll
            for (int q = 0; q < 4; q++) acc[mt][nt][q] = 0.f;

    #pragma unroll
    for (int kk = 0; kk < 8; kk++) {
        int k0 = kk * 16;
        uint32_t ah[2][4], al[2][4];
        #pragma unroll
        for (int mt = 0; mt < 2; mt++) {
            int r = wm * 32 + mt * 16 + l7 + lb3 * 8;
            int c = k0 + lb4 * 8;
            ldsm_x4(ah[mt], (uint32_t)__cvta_generic_to_shared(Xh + r * WPAD + c));
            ldsm_x4(al[mt], (uint32_t)__cvta_generic_to_shared(Xl + r * WPAD + c));
        }
        uint32_t bh[4][2], bl[4][2];
        #pragma unroll
        for (int p = 0; p < 2; p++) {
            int r = k0 + l7 + lb3 * 8;
            int c = wn * 32 + p * 16 + lb4 * 8;
            uint32_t t[4];
            ldsm_x4t(t, (uint32_t)__cvta_generic_to_shared(Wh + r * WPAD + c));
            bh[2*p][0] = t[0]; bh[2*p][1] = t[1]; bh[2*p+1][0] = t[2]; bh[2*p+1][1] = t[3];
            ldsm_x4t(t, (uint32_t)__cvta_generic_to_shared(Wl + r * WPAD + c));
            bl[2*p][0] = t[0]; bl[2*p][1] = t[1]; bl[2*p+1][0] = t[2]; bl[2*p+1][1] = t[3];
        }
        #pragma unroll
        for (int mt = 0; mt < 2; mt++)
            #pragma unroll
            for (int nt = 0; nt < 4; nt++) {
                mma_bf16(acc[mt][nt], ah[mt], bh[nt]);
                mma_bf16(acc[mt][nt], ah[mt], bl[nt]);
                mma_bf16(acc[mt][nt], al[mt], bh[nt]);
            }
    }

    int quad = lane >> 2;
    int tcol = (lane & 3) * 2;
    #pragma unroll
    for (int mt = 0; mt < 2; mt++) {
        int r_lo = row0 + wm * 32 + mt * 16 + quad;
        int r_hi = r_lo + 8;
        float s_lo = (r_lo < n) ? dinv[r_lo] : 0.f;
        float s_hi = (r_hi < n) ? dinv[r_hi] : 0.f;
        #pragma unroll
        for (int nt = 0; nt < 4; nt++) {
            int c = wn * 32 + nt * 8 + tcol;
            if (r_lo < n) {
                __nv_bfloat162 p = __floats2bfloat162_rn(acc[mt][nt][0] * s_lo,
                                                         acc[mt][nt][1] * s_lo);
                *(uint32_t*)(out + (size_t)r_lo * D + c) = *(uint32_t*)&p;
            }
            if (r_hi < n) {
                __nv_bfloat162 p = __floats2bfloat162_rn(acc[mt][nt][2] * s_hi,
                                                         acc[mt][nt][3] * s_hi);
                *(uint32_t*)(out + (size_t)r_hi * D + c) = *(uint32_t*)&p;
            }
        }
    }
}

// ---------------- fused CSR aggregate + post (R6 schedule: 4-pair unroll) ----------------
__device__ __forceinline__ void acc_bf16x8(float* a, uint4 q) {
    __nv_bfloat162 b0 = *(__nv_bfloat162*)&q.x;
    __nv_bfloat162 b1 = *(__nv_bfloat162*)&q.y;
    __nv_bfloat162 b2 = *(__nv_bfloat162*)&q.z;
    __nv_bfloat162 b3 = *(__nv_bfloat162*)&q.w;
    float2 f0 = __bfloat1622float2(b0);
    float2 f1 = __bfloat1622float2(b1);
    float2 f2 = __bfloat1622float2(b2);
    float2 f3 = __bfloat1622float2(b3);
    a[0] += f0.x; a[1] += f0.y; a[2] += f1.x; a[3] += f1.y;
    a[4] += f2.x; a[5] += f2.y; a[6] += f3.x; a[7] += f3.y;
}

__global__ void __launch_bounds__(256)
agg_post_kernel(const __nv_bfloat16* __restrict__ g,
                const int* __restrict__ csr_src, const int* __restrict__ row_start,
                const float* __restrict__ resid,
                const float* __restrict__ dinv,
                const float* __restrict__ bias,
                const float* __restrict__ gamma,
                const float* __restrict__ beta,
                float* __restrict__ h_out,
                const int* __restrict__ batch,
                float* __restrict__ pooled,
                int n, int do_relu, int do_pool) {
    int warp = (blockIdx.x * blockDim.x + threadIdx.x) >> 5;
    int lane = threadIdx.x & 31;
    if (warp >= n) return;

    int half = lane >> 4;
    int hl   = lane & 15;
    int colb = hl * 8;

    int beg = row_start[warp];
    int cnt = row_start[warp + 1] - beg;

    float acc[8];
    #pragma unroll
    for (int k = 0; k < 8; k++) acc[k] = 0.f;

    if (half == 0) {   // self-loop term
        uint4 q = *(const uint4*)(g + (size_t)warp * D + colb);
        acc_bf16x8(acc, q);
    }

    for (int base = 0; base < cnt; base += 32) {
        int m = min(32, cnt - base);
        int idx = (base + lane < cnt) ? __ldg(&csr_src[beg + base + lane]) : 0;
        int j = 0;
        // 4 pairs = 8 edges per iteration
        for (; j + 8 <= m; j += 8) {
            uint4 v[4];
            #pragma unroll
            for (int p = 0; p < 4; p++) {
                int s = __shfl_sync(0xffffffffu, idx, j + 2 * p + half);
                v[p] = *(const uint4*)(g + (size_t)s * D + colb);
            }
            #pragma unroll
            for (int p = 0; p < 4; p++) acc_bf16x8(acc, v[p]);
        }
        for (; j + 2 <= m; j += 2) {
            int s = __shfl_sync(0xffffffffu, idx, j + half);
            uint4 v = *(const uint4*)(g + (size_t)s * D + colb);
            acc_bf16x8(acc, v);
        }
        if (j < m) {   // odd tail: half 0 takes it
            int s = __shfl_sync(0xffffffffu, idx, j);
            if (half == 0) {
                uint4 v = *(const uint4*)(g + (size_t)s * D + colb);
                acc_bf16x8(acc, v);
            }
        }
    }

    #pragma unroll
    for (int k = 0; k < 8; k++)
        acc[k] += __shfl_xor_sync(0xffffffffu, acc[k], 16);

    float sc = dinv[warp];
    float t[8];
    {
        float4 b0 = *(const float4*)(bias + colb);
        float4 b1 = *(const float4*)(bias + colb + 4);
        t[0] = acc[0] * sc + b0.x; t[1] = acc[1] * sc + b0.y;
        t[2] = acc[2] * sc + b0.z; t[3] = acc[3] * sc + b0.w;
        t[4] = acc[4] * sc + b1.x; t[5] = acc[5] * sc + b1.y;
        t[6] = acc[6] * sc + b1.z; t[7] = acc[7] * sc + b1.w;
    }

    float sum = 0.f;
    #pragma unroll
    for (int k = 0; k < 8; k++) sum += t[k];
    #pragma unroll
    for (int o = 16; o > 0; o >>= 1) sum += __shfl_xor_sync(0xffffffffu, sum, o);
    float mu = sum * (1.0f / (2 * D));

    float ss = 0.f;
    #pragma unroll
    for (int k = 0; k < 8; k++) { t[k] -= mu; ss += t[k] * t[k]; }
    #pragma unroll
    for (int o = 16; o > 0; o >>= 1) ss += __shfl_xor_sync(0xffffffffu, ss, o);
    float inv = rsqrtf(ss * (1.0f / (2 * D)) + LN_EPS);

    float y[8];
    {
        float4 g0 = *(const float4*)(gamma + colb);
        float4 g1 = *(const float4*)(gamma + colb + 4);
        float4 e0 = *(const float4*)(beta + colb);
        float4 e1 = *(const float4*)(beta + colb + 4);
        y[0] = t[0] * inv * g0.x + e0.x; y[1] = t[1] * inv * g0.y + e0.y;
        y[2] = t[2] * inv * g0.z + e0.z; y[3] = t[3] * inv * g0.w + e0.w;
        y[4] = t[4] * inv * g1.x + e1.x; y[5] = t[5] * inv * g1.y + e1.y;
        y[6] = t[6] * inv * g1.z + e1.z; y[7] = t[7] * inv * g1.w + e1.w;
    }

    if (resid) {
        float4 r0 = *(const float4*)(resid + (size_t)warp * D + colb);
        float4 r1 = *(const float4*)(resid + (size_t)warp * D + colb + 4);
        y[0] += r0.x; y[1] += r0.y; y[2] += r0.z; y[3] += r0.w;
        y[4] += r1.x; y[5] += r1.y; y[6] += r1.z; y[7] += r1.w;
    }
    if (do_relu) {
        #pragma unroll
        for (int k = 0; k < 8; k++) y[k] = fmaxf(y[k], 0.f);
    }

    if (half == 0) {
        if (do_pool) {
            int b = batch[warp];
            float* p = pooled + (size_t)b * D + colb;
            asm volatile("red.global.add.v4.f32 [%0], {%1,%2,%3,%4};"
                         :: "l"(p), "f"(y[0]), "f"(y[1]), "f"(y[2]), "f"(y[3]) : "memory");
            asm volatile("red.global.add.v4.f32 [%0], {%1,%2,%3,%4};"
                         :: "l"(p + 4), "f"(y[4]), "f"(y[5]), "f"(y[6]), "f"(y[7]) : "memory");
        } else {
            float* p = h_out + (size_t)warp * D + colb;
            *(float4*)p       = make_float4(y[0], y[1], y[2], y[3]);
            *(float4*)(p + 4) = make_float4(y[4], y[5], y[6], y[7]);
        }
    }
}

// ---------------- final readout ----------------
__global__ void out_kernel(const float* __restrict__ pooled, const float* __restrict__ gcnt,
                           const float* __restrict__ lin_w, const float* __restrict__ lin_b,
                           float* __restrict__ out, int ngraphs) {
    int warp = (blockIdx.x * blockDim.x + threadIdx.x) >> 5;
    int lane = threadIdx.x & 31;
    if (warp >= ngraphs) return;
    float acc = 0.f;
    #pragma unroll
    for (int q = 0; q < 4; q++) {
        int j = lane + 32 * q;
        acc += pooled[(size_t)warp * D + j] * lin_w[j];
    }
    #pragma unroll
    for (int o = 16; o > 0; o >>= 1) acc += __shfl_xor_sync(0xffffffffu, acc, o);
    if (lane == 0)
        out[warp] = acc / fmaxf(gcnt[warp], 1.0f) + lin_b[0];
}

// ---------------- host launcher ----------------
extern "C" void kernel_launch(void* const* d_in, const int* in_sizes, int n_in,
                              void* d_out, int out_size) {
    const float* x      = (const float*)d_in[0];
    const void*  ei     = d_in[1];
    const void*  batch  = d_in[2];
    const float* Ws     = (const float*)d_in[3];
    const float* bs     = (const float*)d_in[4];
    const float* gammas = (const float*)d_in[5];
    const float* betas  = (const float*)d_in[6];
    const float* lin_w  = (const float*)d_in[7];
    const float* lin_b  = (const float*)d_in[8];
    float* out = (float*)d_out;

    int n = in_sizes[2];
    int E = in_sizes[1] / 2;
    int ngraphs = out_size;
    if (n > NMAX) n = NMAX;
    if (E > EMAX) E = EMAX;

    __nv_bfloat16 *bufG, *Whi, *Wlo;
    float *bufA, *bufB, *dinv, *pooled, *gcnt;
    int *src, *dst, *csr_src, *cnt_int, *row_start, *wr_ptr, *blockSums, *batch32;
    cudaGetSymbolAddress((void**)&bufG,      d_bufG);
    cudaGetSymbolAddress((void**)&Whi,       d_Whi);
    cudaGetSymbolAddress((void**)&Wlo,       d_Wlo);
    cudaGetSymbolAddress((void**)&bufA,      d_bufA);
    cudaGetSymbolAddress((void**)&bufB,      d_bufB);
    cudaGetSymbolAddress((void**)&dinv,      d_dinv);
    cudaGetSymbolAddress((void**)&src,       d_src);
    cudaGetSymbolAddress((void**)&dst,       d_dst);
    cudaGetSymbolAddress((void**)&csr_src,   d_csr_src);
    cudaGetSymbolAddress((void**)&cnt_int,   d_cnt_int);
    cudaGetSymbolAddress((void**)&row_start, d_row_start);
    cudaGetSymbolAddress((void**)&wr_ptr,    d_wr_ptr);
    cudaGetSymbolAddress((void**)&blockSums, d_blockSums);
    cudaGetSymbolAddress((void**)&batch32,   d_batch32);
    cudaGetSymbolAddress((void**)&pooled,    d_pooled);
    cudaGetSymbolAddress((void**)&gcnt,      d_gcnt);

    const int smem_bytes = (2 * 128 * WPAD + 2 * 64 * WPAD) * sizeof(__nv_bfloat16);
    cudaFuncSetAttribute(gemm_kernel, cudaFuncAttributeMaxDynamicSharedMemorySize, smem_bytes);

    // ---- preamble ----
    detect_kernel<<<1, 32>>>((const int*)ei);
    cudaMemsetAsync(cnt_int, 0, (size_t)n * sizeof(int));
    cudaMemsetAsync(gcnt, 0, (size_t)ngraphs * sizeof(float));
    cudaMemsetAsync(pooled, 0, (size_t)ngraphs * D * sizeof(float));

    wsplit_kernel<<<(NLAYER * D * D + 255) / 256, 256>>>(Ws, Whi, Wlo);
    cvt_hist_kernel<<<(E + 255) / 256, 256>>>(ei, src, dst, cnt_int, E, n);
    cvt_batch_kernel<<<(n + 255) / 256, 256>>>(batch, batch32, gcnt, n);

    int nb = (n + SCAN_BLOCK - 1) / SCAN_BLOCK;
    scanA_kernel<<<nb, SCAN_TPB>>>(cnt_int, row_start, blockSums, n);
    scanB_kernel<<<1, SCAN_MAXBLOCKS>>>(blockSums, nb);
    scanC_kernel<<<(n + 255) / 256, 256>>>(row_start, blockSums, wr_ptr, cnt_int, dinv, n, E);
    scatter_kernel<<<(E + 255) / 256, 256>>>(src, dst, wr_ptr, csr_src, E);

    // ---- layers ----
    int gemm_blocks = (n + 63) / 64;
    int row_warp_blocks = (n + 7) / 8;
    const float* in_ptr = x;
    float* hbufs[2] = {bufA, bufB};
    for (int l = 0; l < 4; l++) {
        gemm_kernel<<<gemm_blocks, 256, smem_bytes>>>(in_ptr, Whi + (size_t)l * D * D,
                                                      Wlo + (size_t)l * D * D, dinv, bufG, n);
        float* h_out = hbufs[l & 1];
        int do_pool = (l == 3);
        agg_post_kernel<<<row_warp_blocks, 256>>>(bufG, csr_src, row_start,
                                                  (l == 0) ? nullptr : in_ptr,
                                                  dinv,
                                                  bs + l * D, gammas + l * D, betas + l * D,
                                                  h_out, batch32, pooled,
                                                  n, (l < 3) ? 1 : 0, do_pool);
        in_ptr = h_out;
    }

    out_kernel<<<(ngraphs * 32 + 255) / 256, 256>>>(pooled, gcnt, lin_w, lin_b, out, ngraphs);
}

// round 9
// speedup vs baseline: 1.2740x; 1.1781x over previous
#include <cuda_runtime.h>
#include <cuda_bf16.h>
#include <stdint.h>

#define D 128
#define NMAX 100000
#define EMAX 1600000
#define NGRAPH 512
#define NLAYER 4
#define LN_EPS 1e-5f

#define SCAN_TPB 256
#define SCAN_ITEMS 8
#define SCAN_BLOCK (SCAN_TPB * SCAN_ITEMS)   // 2048
#define SCAN_MAXBLOCKS 1024

// ---------------- scratch (no allocs allowed) ----------------
__device__ __nv_bfloat16 d_bufG[(size_t)NMAX * D];   // g = (in @ W) * dinv[row], bf16
__device__ __nv_bfloat16 d_bufA[(size_t)NMAX * D];   // h buffers, bf16
__device__ __nv_bfloat16 d_bufB[(size_t)NMAX * D];
__device__ __nv_bfloat16 d_Whi[NLAYER * D * D];
__device__ __nv_bfloat16 d_Wlo[NLAYER * D * D];
__device__ float d_dinv[NMAX];
__device__ int   d_src[EMAX];
__device__ int   d_dst[EMAX];
__device__ int   d_csr_src[EMAX];
__device__ int   d_cnt_int[NMAX];
__device__ int   d_row_start[NMAX + 1];
__device__ int   d_wr_ptr[NMAX];
__device__ int   d_blockSums[SCAN_MAXBLOCKS];
__device__ int   d_batch32[NMAX];
__device__ float d_pooled[NGRAPH * D];
__device__ float d_gcnt[NGRAPH];
__device__ int   d_is64;

// ---------------- dtype detection: int64 vs int32 indices ----------------
__global__ void detect_kernel(const int* __restrict__ w) {
    if (threadIdx.x == 0 && blockIdx.x == 0) {
        int zeros = 0;
        #pragma unroll
        for (int k = 0; k < 64; k++)
            if (w[2 * k + 1] == 0) zeros++;
        d_is64 = (zeros == 64) ? 1 : 0;
    }
}

// ---------------- W hi/lo split (once for all layers) ----------------
__global__ void wsplit_kernel(const float* __restrict__ Ws,
                              __nv_bfloat16* __restrict__ Whi,
                              __nv_bfloat16* __restrict__ Wlo) {
    int i = blockIdx.x * blockDim.x + threadIdx.x;
    if (i >= NLAYER * D * D) return;
    float w = Ws[i];
    __nv_bfloat16 h = __float2bfloat16(w);
    Whi[i] = h;
    Wlo[i] = __float2bfloat16(w - __bfloat162float(h));
}

// ---------------- fused: convert edges + degree histogram ----------------
__global__ void cvt_hist_kernel(const void* __restrict__ ei,
                                int* __restrict__ src, int* __restrict__ dst,
                                int* __restrict__ cnt, int E, int n) {
    int i = blockIdx.x * blockDim.x + threadIdx.x;
    if (i >= E) return;
    int s, d2;
    if (d_is64) {
        const long long* p = (const long long*)ei;
        s  = (int)p[i];
        d2 = (int)p[(size_t)E + i];
    } else {
        const int* p = (const int*)ei;
        s  = p[i];
        d2 = p[E + i];
    }
    s  = min(max(s, 0), n - 1);
    d2 = min(max(d2, 0), n - 1);
    src[i] = s;
    dst[i] = d2;
    atomicAdd(&cnt[d2], 1);
}

// ---------------- convert batch + graph counts (smem-aggregated) ----------------
__global__ void cvt_batch_kernel(const void* __restrict__ b,
                                 int* __restrict__ outb,
                                 float* __restrict__ gcnt, int n) {
    __shared__ int hist[NGRAPH];
    for (int k = threadIdx.x; k < NGRAPH; k += blockDim.x) hist[k] = 0;
    __syncthreads();
    int i = blockIdx.x * blockDim.x + threadIdx.x;
    if (i < n) {
        int v;
        if (d_is64) v = (int)((const long long*)b)[i];
        else        v = ((const int*)b)[i];
        v = min(max(v, 0), NGRAPH - 1);
        outb[i] = v;
        atomicAdd(&hist[v], 1);
    }
    __syncthreads();
    for (int k = threadIdx.x; k < NGRAPH; k += blockDim.x) {
        int c = hist[k];
        if (c) atomicAdd(&gcnt[k], (float)c);
    }
}

// ---------------- exclusive scan (3 kernels) ----------------
__global__ void scanA_kernel(const int* __restrict__ cnt, int* __restrict__ row_start,
                             int* __restrict__ blockSums, int n) {
    __shared__ int ssum[SCAN_TPB];
    int b = blockIdx.x, t = threadIdx.x;
    int base = b * SCAN_BLOCK + t * SCAN_ITEMS;
    int v[SCAN_ITEMS];
    int s = 0;
    #pragma unroll
    for (int i = 0; i < SCAN_ITEMS; i++) {
        v[i] = (base + i < n) ? cnt[base + i] : 0;
        s += v[i];
    }
    ssum[t] = s;
    __syncthreads();
    for (int off = 1; off < SCAN_TPB; off <<= 1) {
        int x = (t >= off) ? ssum[t - off] : 0;
        __syncthreads();
        ssum[t] += x;
        __syncthreads();
    }
    int run = ssum[t] - s;
    #pragma unroll
    for (int i = 0; i < SCAN_ITEMS; i++) {
        if (base + i < n) row_start[base + i] = run;
        run += v[i];
    }
    if (t == SCAN_TPB - 1) blockSums[b] = ssum[t];
}

__global__ void scanB_kernel(int* __restrict__ blockSums, int nb) {
    __shared__ int ssum[SCAN_MAXBLOCKS];
    int t = threadIdx.x;
    int v = (t < nb) ? blockSums[t] : 0;
    ssum[t] = v;
    __syncthreads();
    for (int off = 1; off < SCAN_MAXBLOCKS; off <<= 1) {
        int x = (t >= off) ? ssum[t - off] : 0;
        __syncthreads();
        ssum[t] += x;
        __syncthreads();
    }
    if (t < nb) blockSums[t] = ssum[t] - v;
}

__global__ void scanC_kernel(int* __restrict__ row_start, const int* __restrict__ blockSums,
                             int* __restrict__ wr_ptr, const int* __restrict__ cnt,
                             float* __restrict__ dinv, int n, int E) {
    int i = blockIdx.x * blockDim.x + threadIdx.x;
    if (i < n) {
        int v = row_start[i] + blockSums[i / SCAN_BLOCK];
        row_start[i] = v;
        wr_ptr[i] = v;
        dinv[i] = rsqrtf((float)cnt[i] + 1.0f);
    }
    if (i == 0) row_start[n] = E;
}

__global__ void scatter_kernel(const int* __restrict__ src, const int* __restrict__ dst,
                               int* __restrict__ wr_ptr, int* __restrict__ csr_src, int E) {
    int e = blockIdx.x * blockDim.x + threadIdx.x;
    if (e < E) {
        int p = atomicAdd(&wr_ptr[dst[e]], 1);
        csr_src[p] = src[e];
    }
}

// ---------------- tensor-core GEMM: g = bf16((in @ W) * dinv[row]) ----------------
// XF32: layer-0 path (fp32 input, hi/lo X split, 3 MMAs/tile)
// !XF32: bf16 input is exact -> Xl==0 -> 2 MMAs/tile, straight-copy staging
#define WPAD 136

__device__ __forceinline__ void ldsm_x4(uint32_t* r, uint32_t addr) {
    asm volatile("ldmatrix.sync.aligned.m8n8.x4.shared.b16 {%0,%1,%2,%3}, [%4];"
                 : "=r"(r[0]), "=r"(r[1]), "=r"(r[2]), "=r"(r[3]) : "r"(addr));
}
__device__ __forceinline__ void ldsm_x4t(uint32_t* r, uint32_t addr) {
    asm volatile("ldmatrix.sync.aligned.m8n8.x4.trans.shared.b16 {%0,%1,%2,%3}, [%4];"
                 : "=r"(r[0]), "=r"(r[1]), "=r"(r[2]), "=r"(r[3]) : "r"(addr));
}
__device__ __forceinline__ void mma_bf16(float* c, const uint32_t* a, const uint32_t* b) {
    asm volatile("mma.sync.aligned.m16n8k16.row.col.f32.bf16.bf16.f32 "
                 "{%0,%1,%2,%3}, {%4,%5,%6,%7}, {%8,%9}, {%0,%1,%2,%3};"
                 : "+f"(c[0]), "+f"(c[1]), "+f"(c[2]), "+f"(c[3])
                 : "r"(a[0]), "r"(a[1]), "r"(a[2]), "r"(a[3]), "r"(b[0]), "r"(b[1]));
}

template <bool XF32>
__global__ void __launch_bounds__(256, 2)
gemm_kernel(const void* __restrict__ in,
            const __nv_bfloat16* __restrict__ WhiG,
            const __nv_bfloat16* __restrict__ WloG,
            const float* __restrict__ dinv, __nv_bfloat16* __restrict__ out, int n) {
    extern __shared__ __nv_bfloat16 sm[];
    __nv_bfloat16* Wh = sm;
    __nv_bfloat16* Wl = Wh + 128 * WPAD;
    __nv_bfloat16* Xh = Wl + 128 * WPAD;
    __nv_bfloat16* Xl = Xh + 64 * WPAD;   // used only when XF32

    int tid  = threadIdx.x;
    int row0 = blockIdx.x * 64;

    // stage pre-split W: straight uint4 copies
    {
        const uint4* src_h = (const uint4*)WhiG;
        const uint4* src_l = (const uint4*)WloG;
        #pragma unroll
        for (int i = tid; i < 2048; i += 256) {
            int r = i >> 4;
            int c = (i & 15) * 8;
            *(uint4*)(Wh + r * WPAD + c) = src_h[i];
            *(uint4*)(Wl + r * WPAD + c) = src_l[i];
        }
    }
    if (XF32) {
        const float* inf = (const float*)in;
        #pragma unroll
        for (int i = tid; i < 64 * 32; i += 256) {
            int r = i >> 5, c = (i & 31) * 4;
            float4 v = make_float4(0.f, 0.f, 0.f, 0.f);
            if (row0 + r < n)
                v = *(const float4*)(inf + (size_t)(row0 + r) * D + c);
            __nv_bfloat16 h0 = __float2bfloat16(v.x);
            __nv_bfloat16 h1 = __float2bfloat16(v.y);
            __nv_bfloat16 h2 = __float2bfloat16(v.z);
            __nv_bfloat16 h3 = __float2bfloat16(v.w);
            __nv_bfloat16* ph = Xh + r * WPAD + c;
            __nv_bfloat16* pl = Xl + r * WPAD + c;
            ph[0] = h0; ph[1] = h1; ph[2] = h2; ph[3] = h3;
            pl[0] = __float2bfloat16(v.x - __bfloat162float(h0));
            pl[1] = __float2bfloat16(v.y - __bfloat162float(h1));
            pl[2] = __float2bfloat16(v.z - __bfloat162float(h2));
            pl[3] = __float2bfloat16(v.w - __bfloat162float(h3));
        }
    } else {
        const __nv_bfloat16* inb = (const __nv_bfloat16*)in;
        #pragma unroll
        for (int i = tid; i < 64 * 16; i += 256) {
            int r = i >> 4, c = (i & 15) * 8;
            uint4 v = make_uint4(0u, 0u, 0u, 0u);
            if (row0 + r < n)
                v = *(const uint4*)(inb + (size_t)(row0 + r) * D + c);
            *(uint4*)(Xh + r * WPAD + c) = v;
        }
    }
    __syncthreads();

    int wid  = tid >> 5;
    int lane = tid & 31;
    int wm = wid >> 2;
    int wn = wid & 3;

    int l7  = lane & 7;
    int lb3 = (lane >> 3) & 1;
    int lb4 = (lane >> 4) & 1;

    float acc[2][4][4];
    #pragma unroll
    for (int mt = 0; mt < 2; mt++)
        #pragma unroll
        for (int nt = 0; nt < 4; nt++)
            #pragma unroll
            for (int q = 0; q < 4; q++) acc[mt][nt][q] = 0.f;

    #pragma unroll
    for (int kk = 0; kk < 8; kk++) {
        int k0 = kk * 16;
        uint32_t ah[2][4], al[2][4];
        #pragma unroll
        for (int mt = 0; mt < 2; mt++) {
            int r = wm * 32 + mt * 16 + l7 + lb3 * 8;
            int c = k0 + lb4 * 8;
            ldsm_x4(ah[mt], (uint32_t)__cvta_generic_to_shared(Xh + r * WPAD + c));
            if (XF32)
                ldsm_x4(al[mt], (uint32_t)__cvta_generic_to_shared(Xl + r * WPAD + c));
        }
        uint32_t bh[4][2], bl[4][2];
        #pragma unroll
        for (int p = 0; p < 2; p++) {
            int r = k0 + l7 + lb3 * 8;
            int c = wn * 32 + p * 16 + lb4 * 8;
            uint32_t t[4];
            ldsm_x4t(t, (uint32_t)__cvta_generic_to_shared(Wh + r * WPAD + c));
            bh[2*p][0] = t[0]; bh[2*p][1] = t[1]; bh[2*p+1][0] = t[2]; bh[2*p+1][1] = t[3];
            ldsm_x4t(t, (uint32_t)__cvta_generic_to_shared(Wl + r * WPAD + c));
            bl[2*p][0] = t[0]; bl[2*p][1] = t[1]; bl[2*p+1][0] = t[2]; bl[2*p+1][1] = t[3];
        }
        #pragma unroll
        for (int mt = 0; mt < 2; mt++)
            #pragma unroll
            for (int nt = 0; nt < 4; nt++) {
                mma_bf16(acc[mt][nt], ah[mt], bh[nt]);
                mma_bf16(acc[mt][nt], ah[mt], bl[nt]);
                if (XF32)
                    mma_bf16(acc[mt][nt], al[mt], bh[nt]);
            }
    }

    int quad = lane >> 2;
    int tcol = (lane & 3) * 2;
    #pragma unroll
    for (int mt = 0; mt < 2; mt++) {
        int r_lo = row0 + wm * 32 + mt * 16 + quad;
        int r_hi = r_lo + 8;
        float s_lo = (r_lo < n) ? dinv[r_lo] : 0.f;
        float s_hi = (r_hi < n) ? dinv[r_hi] : 0.f;
        #pragma unroll
        for (int nt = 0; nt < 4; nt++) {
            int c = wn * 32 + nt * 8 + tcol;
            if (r_lo < n) {
                __nv_bfloat162 p = __floats2bfloat162_rn(acc[mt][nt][0] * s_lo,
                                                         acc[mt][nt][1] * s_lo);
                *(uint32_t*)(out + (size_t)r_lo * D + c) = *(uint32_t*)&p;
            }
            if (r_hi < n) {
                __nv_bfloat162 p = __floats2bfloat162_rn(acc[mt][nt][2] * s_hi,
                                                         acc[mt][nt][3] * s_hi);
                *(uint32_t*)(out + (size_t)r_hi * D + c) = *(uint32_t*)&p;
            }
        }
    }
}

// ---------------- fused CSR aggregate + post (bf16 h in/out) ----------------
__device__ __forceinline__ void acc_bf16x8(float* a, uint4 q) {
    __nv_bfloat162 b0 = *(__nv_bfloat162*)&q.x;
    __nv_bfloat162 b1 = *(__nv_bfloat162*)&q.y;
    __nv_bfloat162 b2 = *(__nv_bfloat162*)&q.z;
    __nv_bfloat162 b3 = *(__nv_bfloat162*)&q.w;
    float2 f0 = __bfloat1622float2(b0);
    float2 f1 = __bfloat1622float2(b1);
    float2 f2 = __bfloat1622float2(b2);
    float2 f3 = __bfloat1622float2(b3);
    a[0] += f0.x; a[1] += f0.y; a[2] += f1.x; a[3] += f1.y;
    a[4] += f2.x; a[5] += f2.y; a[6] += f3.x; a[7] += f3.y;
}

__global__ void __launch_bounds__(256)
agg_post_kernel(const __nv_bfloat16* __restrict__ g,
                const int* __restrict__ csr_src, const int* __restrict__ row_start,
                const __nv_bfloat16* __restrict__ resid,
                const float* __restrict__ dinv,
                const float* __restrict__ bias,
                const float* __restrict__ gamma,
                const float* __restrict__ beta,
                __nv_bfloat16* __restrict__ h_out,
                const int* __restrict__ batch,
                float* __restrict__ pooled,
                int n, int do_relu, int do_pool) {
    int warp = (blockIdx.x * blockDim.x + threadIdx.x) >> 5;
    int lane = threadIdx.x & 31;
    if (warp >= n) return;

    int half = lane >> 4;
    int hl   = lane & 15;
    int colb = hl * 8;

    int beg = row_start[warp];
    int cnt = row_start[warp + 1] - beg;

    float acc[8];
    #pragma unroll
    for (int k = 0; k < 8; k++) acc[k] = 0.f;

    if (half == 0) {   // self-loop term
        uint4 q = *(const uint4*)(g + (size_t)warp * D + colb);
        acc_bf16x8(acc, q);
    }

    for (int base = 0; base < cnt; base += 32) {
        int m = min(32, cnt - base);
        int idx = (base + lane < cnt) ? __ldg(&csr_src[beg + base + lane]) : 0;
        int j = 0;
        for (; j + 8 <= m; j += 8) {
            uint4 v[4];
            #pragma unroll
            for (int p = 0; p < 4; p++) {
                int s = __shfl_sync(0xffffffffu, idx, j + 2 * p + half);
                v[p] = *(const uint4*)(g + (size_t)s * D + colb);
            }
            #pragma unroll
            for (int p = 0; p < 4; p++) acc_bf16x8(acc, v[p]);
        }
        for (; j + 2 <= m; j += 2) {
            int s = __shfl_sync(0xffffffffu, idx, j + half);
            uint4 v = *(const uint4*)(g + (size_t)s * D + colb);
            acc_bf16x8(acc, v);
        }
        if (j < m) {
            int s = __shfl_sync(0xffffffffu, idx, j);
            if (half == 0) {
                uint4 v = *(const uint4*)(g + (size_t)s * D + colb);
                acc_bf16x8(acc, v);
            }
        }
    }

    #pragma unroll
    for (int k = 0; k < 8; k++)
        acc[k] += __shfl_xor_sync(0xffffffffu, acc[k], 16);

    float sc = dinv[warp];
    float t[8];
    {
        float4 b0 = *(const float4*)(bias + colb);
        float4 b1 = *(const float4*)(bias + colb + 4);
        t[0] = acc[0] * sc + b0.x; t[1] = acc[1] * sc + b0.y;
        t[2] = acc[2] * sc + b0.z; t[3] = acc[3] * sc + b0.w;
        t[4] = acc[4] * sc + b1.x; t[5] = acc[5] * sc + b1.y;
        t[6] = acc[6] * sc + b1.z; t[7] = acc[7] * sc + b1.w;
    }

    float sum = 0.f;
    #pragma unroll
    for (int k = 0; k < 8; k++) sum += t[k];
    #pragma unroll
    for (int o = 16; o > 0; o >>= 1) sum += __shfl_xor_sync(0xffffffffu, sum, o);
    float mu = sum * (1.0f / (2 * D));

    float ss = 0.f;
    #pragma unroll
    for (int k = 0; k < 8; k++) { t[k] -= mu; ss += t[k] * t[k]; }
    #pragma unroll
    for (int o = 16; o > 0; o >>= 1) ss += __shfl_xor_sync(0xffffffffu, ss, o);
    float inv = rsqrtf(ss * (1.0f / (2 * D)) + LN_EPS);

    float y[8];
    {
        float4 g0 = *(const float4*)(gamma + colb);
        float4 g1 = *(const float4*)(gamma + colb + 4);
        float4 e0 = *(const float4*)(beta + colb);
        float4 e1 = *(const float4*)(beta + colb + 4);
        y[0] = t[0] * inv * g0.x + e0.x; y[1] = t[1] * inv * g0.y + e0.y;
        y[2] = t[2] * inv * g0.z + e0.z; y[3] = t[3] * inv * g0.w + e0.w;
        y[4] = t[4] * inv * g1.x + e1.x; y[5] = t[5] * inv * g1.y + e1.y;
        y[6] = t[6] * inv * g1.z + e1.z; y[7] = t[7] * inv * g1.w + e1.w;
    }

    if (resid) {
        uint4 r = *(const uint4*)(resid + (size_t)warp * D + colb);
        float racc[8] = {0, 0, 0, 0, 0, 0, 0, 0};
        acc_bf16x8(racc, r);
        #pragma unroll
        for (int k = 0; k < 8; k++) y[k] += racc[k];
    }
    if (do_relu) {
        #pragma unroll
        for (int k = 0; k < 8; k++) y[k] = fmaxf(y[k], 0.f);
    }

    if (half == 0) {
        if (do_pool) {
            int b = batch[warp];
            float* p = pooled + (size_t)b * D + colb;
            asm volatile("red.global.add.v4.f32 [%0], {%1,%2,%3,%4};"
                         :: "l"(p), "f"(y[0]), "f"(y[1]), "f"(y[2]), "f"(y[3]) : "memory");
            asm volatile("red.global.add.v4.f32 [%0], {%1,%2,%3,%4};"
                         :: "l"(p + 4), "f"(y[4]), "f"(y[5]), "f"(y[6]), "f"(y[7]) : "memory");
        } else {
            __nv_bfloat162 p0 = __floats2bfloat162_rn(y[0], y[1]);
            __nv_bfloat162 p1 = __floats2bfloat162_rn(y[2], y[3]);
            __nv_bfloat162 p2 = __floats2bfloat162_rn(y[4], y[5]);
            __nv_bfloat162 p3 = __floats2bfloat162_rn(y[6], y[7]);
            uint4 o;
            o.x = *(uint32_t*)&p0; o.y = *(uint32_t*)&p1;
            o.z = *(uint32_t*)&p2; o.w = *(uint32_t*)&p3;
            *(uint4*)(h_out + (size_t)warp * D + colb) = o;
        }
    }
}

// ---------------- final readout ----------------
__global__ void out_kernel(const float* __restrict__ pooled, const float* __restrict__ gcnt,
                           const float* __restrict__ lin_w, const float* __restrict__ lin_b,
                           float* __restrict__ out, int ngraphs) {
    int warp = (blockIdx.x * blockDim.x + threadIdx.x) >> 5;
    int lane = threadIdx.x & 31;
    if (warp >= ngraphs) return;
    float acc = 0.f;
    #pragma unroll
    for (int q = 0; q < 4; q++) {
        int j = lane + 32 * q;
        acc += pooled[(size_t)warp * D + j] * lin_w[j];
    }
    #pragma unroll
    for (int o = 16; o > 0; o >>= 1) acc += __shfl_xor_sync(0xffffffffu, acc, o);
    if (lane == 0)
        out[warp] = acc / fmaxf(gcnt[warp], 1.0f) + lin_b[0];
}

// ---------------- host launcher ----------------
extern "C" void kernel_launch(void* const* d_in, const int* in_sizes, int n_in,
                              void* d_out, int out_size) {
    const float* x      = (const float*)d_in[0];
    const void*  ei     = d_in[1];
    const void*  batch  = d_in[2];
    const float* Ws     = (const float*)d_in[3];
    const float* bs     = (const float*)d_in[4];
    const float* gammas = (const float*)d_in[5];
    const float* betas  = (const float*)d_in[6];
    const float* lin_w  = (const float*)d_in[7];
    const float* lin_b  = (const float*)d_in[8];
    float* out = (float*)d_out;

    int n = in_sizes[2];
    int E = in_sizes[1] / 2;
    int ngraphs = out_size;
    if (n > NMAX) n = NMAX;
    if (E > EMAX) E = EMAX;

    __nv_bfloat16 *bufG, *bufA, *bufB, *Whi, *Wlo;
    float *dinv, *pooled, *gcnt;
    int *src, *dst, *csr_src, *cnt_int, *row_start, *wr_ptr, *blockSums, *batch32;
    cudaGetSymbolAddress((void**)&bufG,      d_bufG);
    cudaGetSymbolAddress((void**)&Whi,       d_Whi);
    cudaGetSymbolAddress((void**)&Wlo,       d_Wlo);
    cudaGetSymbolAddress((void**)&bufA,      d_bufA);
    cudaGetSymbolAddress((void**)&bufB,      d_bufB);
    cudaGetSymbolAddress((void**)&dinv,      d_dinv);
    cudaGetSymbolAddress((void**)&src,       d_src);
    cudaGetSymbolAddress((void**)&dst,       d_dst);
    cudaGetSymbolAddress((void**)&csr_src,   d_csr_src);
    cudaGetSymbolAddress((void**)&cnt_int,   d_cnt_int);
    cudaGetSymbolAddress((void**)&row_start, d_row_start);
    cudaGetSymbolAddress((void**)&wr_ptr,    d_wr_ptr);
    cudaGetSymbolAddress((void**)&blockSums, d_blockSums);
    cudaGetSymbolAddress((void**)&batch32,   d_batch32);
    cudaGetSymbolAddress((void**)&pooled,    d_pooled);
    cudaGetSymbolAddress((void**)&gcnt,      d_gcnt);

    const int smem_bytes = (2 * 128 * WPAD + 2 * 64 * WPAD) * sizeof(__nv_bfloat16);
    cudaFuncSetAttribute(gemm_kernel<true>, cudaFuncAttributeMaxDynamicSharedMemorySize, smem_bytes);
    cudaFuncSetAttribute(gemm_kernel<false>, cudaFuncAttributeMaxDynamicSharedMemorySize, smem_bytes);

    // ---- preamble ----
    detect_kernel<<<1, 32>>>((const int*)ei);
    cudaMemsetAsync(cnt_int, 0, (size_t)n * sizeof(int));
    cudaMemsetAsync(gcnt, 0, (size_t)ngraphs * sizeof(float));
    cudaMemsetAsync(pooled, 0, (size_t)ngraphs * D * sizeof(float));

    wsplit_kernel<<<(NLAYER * D * D + 255) / 256, 256>>>(Ws, Whi, Wlo);
    cvt_hist_kernel<<<(E + 255) / 256, 256>>>(ei, src, dst, cnt_int, E, n);
    cvt_batch_kernel<<<(n + 255) / 256, 256>>>(batch, batch32, gcnt, n);

    int nb = (n + SCAN_BLOCK - 1) / SCAN_BLOCK;
    scanA_kernel<<<nb, SCAN_TPB>>>(cnt_int, row_start, blockSums, n);
    scanB_kernel<<<1, SCAN_MAXBLOCKS>>>(blockSums, nb);
    scanC_kernel<<<(n + 255) / 256, 256>>>(row_start, blockSums, wr_ptr, cnt_int, dinv, n, E);
    scatter_kernel<<<(E + 255) / 256, 256>>>(src, dst, wr_ptr, csr_src, E);

    // ---- layers ----
    int gemm_blocks = (n + 63) / 64;
    int row_warp_blocks = (n + 7) / 8;
    const void* in_ptr = x;
    __nv_bfloat16* hbufs[2] = {bufA, bufB};
    for (int l = 0; l < 4; l++) {
        if (l == 0)
            gemm_kernel<true><<<gemm_blocks, 256, smem_bytes>>>(in_ptr, Whi, Wlo, dinv, bufG, n);
        else
            gemm_kernel<false><<<gemm_blocks, 256, smem_bytes>>>(in_ptr, Whi + (size_t)l * D * D,
                                                                 Wlo + (size_t)l * D * D, dinv, bufG, n);
        __nv_bfloat16* h_out = hbufs[l & 1];
        int do_pool = (l == 3);
        agg_post_kernel<<<row_warp_blocks, 256>>>(bufG, csr_src, row_start,
                                                  (l == 0) ? nullptr : (const __nv_bfloat16*)in_ptr,
                                                  dinv,
                                                  bs + l * D, gammas + l * D, betas + l * D,
                                                  h_out, batch32, pooled,
                                                  n, (l < 3) ? 1 : 0, do_pool);
        in_ptr = h_out;
    }

    out_kernel<<<(ngraphs * 32 + 255) / 256, 256>>>(pooled, gcnt, lin_w, lin_b, out, ngraphs);
}

// round 10
// speedup vs baseline: 1.3289x; 1.0431x over previous
#include <cuda_runtime.h>
#include <cuda_bf16.h>
#include <stdint.h>

#define D 128
#define NMAX 100000
#define EMAX 1600000
#define NGRAPH 512
#define NLAYER 4
#define LN_EPS 1e-5f

#define SCAN_TPB 256
#define SCAN_ITEMS 8
#define SCAN_BLOCK (SCAN_TPB * SCAN_ITEMS)   // 2048
#define SCAN_MAXBLOCKS 1024

#define GEMM_GRID 296   // 2 blocks per SM (148 SMs)

// ---------------- scratch (no allocs allowed) ----------------
__device__ __nv_bfloat16 d_bufG[(size_t)NMAX * D];   // g = (in @ W) * dinv[row], bf16
__device__ __nv_bfloat16 d_bufA[(size_t)NMAX * D];   // h buffers, bf16
__device__ __nv_bfloat16 d_bufB[(size_t)NMAX * D];
__device__ __nv_bfloat16 d_Whi[NLAYER * D * D];
__device__ __nv_bfloat16 d_Wlo[NLAYER * D * D];
__device__ float d_dinv[NMAX];
__device__ int   d_src[EMAX];
__device__ int   d_dst[EMAX];
__device__ int   d_csr_src[EMAX];
__device__ int   d_cnt_int[NMAX];
__device__ int   d_row_start[NMAX + 1];
__device__ int   d_wr_ptr[NMAX];
__device__ int   d_blockSums[SCAN_MAXBLOCKS];
__device__ int   d_batch32[NMAX];
__device__ float d_pooled[NGRAPH * D];
__device__ float d_gcnt[NGRAPH];
__device__ int   d_is64;

// ---------------- dtype detection: int64 vs int32 indices ----------------
__global__ void detect_kernel(const int* __restrict__ w) {
    if (threadIdx.x == 0 && blockIdx.x == 0) {
        int zeros = 0;
        #pragma unroll
        for (int k = 0; k < 64; k++)
            if (w[2 * k + 1] == 0) zeros++;
        d_is64 = (zeros == 64) ? 1 : 0;
    }
}

// ---------------- W hi/lo split (once for all layers) ----------------
__global__ void wsplit_kernel(const float* __restrict__ Ws,
                              __nv_bfloat16* __restrict__ Whi,
                              __nv_bfloat16* __restrict__ Wlo) {
    int i = blockIdx.x * blockDim.x + threadIdx.x;
    if (i >= NLAYER * D * D) return;
    float w = Ws[i];
    __nv_bfloat16 h = __float2bfloat16(w);
    Whi[i] = h;
    Wlo[i] = __float2bfloat16(w - __bfloat162float(h));
}

// ---------------- fused: convert edges + degree histogram ----------------
__global__ void cvt_hist_kernel(const void* __restrict__ ei,
                                int* __restrict__ src, int* __restrict__ dst,
                                int* __restrict__ cnt, int E, int n) {
    int i = blockIdx.x * blockDim.x + threadIdx.x;
    if (i >= E) return;
    int s, d2;
    if (d_is64) {
        const long long* p = (const long long*)ei;
        s  = (int)p[i];
        d2 = (int)p[(size_t)E + i];
    } else {
        const int* p = (const int*)ei;
        s  = p[i];
        d2 = p[E + i];
    }
    s  = min(max(s, 0), n - 1);
    d2 = min(max(d2, 0), n - 1);
    src[i] = s;
    dst[i] = d2;
    atomicAdd(&cnt[d2], 1);
}

// ---------------- convert batch + graph counts (smem-aggregated) ----------------
__global__ void cvt_batch_kernel(const void* __restrict__ b,
                                 int* __restrict__ outb,
                                 float* __restrict__ gcnt, int n) {
    __shared__ int hist[NGRAPH];
    for (int k = threadIdx.x; k < NGRAPH; k += blockDim.x) hist[k] = 0;
    __syncthreads();
    int i = blockIdx.x * blockDim.x + threadIdx.x;
    if (i < n) {
        int v;
        if (d_is64) v = (int)((const long long*)b)[i];
        else        v = ((const int*)b)[i];
        v = min(max(v, 0), NGRAPH - 1);
        outb[i] = v;
        atomicAdd(&hist[v], 1);
    }
    __syncthreads();
    for (int k = threadIdx.x; k < NGRAPH; k += blockDim.x) {
        int c = hist[k];
        if (c) atomicAdd(&gcnt[k], (float)c);
    }
}

// ---------------- exclusive scan (3 kernels) ----------------
__global__ void scanA_kernel(const int* __restrict__ cnt, int* __restrict__ row_start,
                             int* __restrict__ blockSums, int n) {
    __shared__ int ssum[SCAN_TPB];
    int b = blockIdx.x, t = threadIdx.x;
    int base = b * SCAN_BLOCK + t * SCAN_ITEMS;
    int v[SCAN_ITEMS];
    int s = 0;
    #pragma unroll
    for (int i = 0; i < SCAN_ITEMS; i++) {
        v[i] = (base + i < n) ? cnt[base + i] : 0;
        s += v[i];
    }
    ssum[t] = s;
    __syncthreads();
    for (int off = 1; off < SCAN_TPB; off <<= 1) {
        int x = (t >= off) ? ssum[t - off] : 0;
        __syncthreads();
        ssum[t] += x;
        __syncthreads();
    }
    int run = ssum[t] - s;
    #pragma unroll
    for (int i = 0; i < SCAN_ITEMS; i++) {
        if (base + i < n) row_start[base + i] = run;
        run += v[i];
    }
    if (t == SCAN_TPB - 1) blockSums[b] = ssum[t];
}

__global__ void scanB_kernel(int* __restrict__ blockSums, int nb) {
    __shared__ int ssum[SCAN_MAXBLOCKS];
    int t = threadIdx.x;
    int v = (t < nb) ? blockSums[t] : 0;
    ssum[t] = v;
    __syncthreads();
    for (int off = 1; off < SCAN_MAXBLOCKS; off <<= 1) {
        int x = (t >= off) ? ssum[t - off] : 0;
        __syncthreads();
        ssum[t] += x;
        __syncthreads();
    }
    if (t < nb) blockSums[t] = ssum[t] - v;
}

__global__ void scanC_kernel(int* __restrict__ row_start, const int* __restrict__ blockSums,
                             int* __restrict__ wr_ptr, const int* __restrict__ cnt,
                             float* __restrict__ dinv, int n, int E) {
    int i = blockIdx.x * blockDim.x + threadIdx.x;
    if (i < n) {
        int v = row_start[i] + blockSums[i / SCAN_BLOCK];
        row_start[i] = v;
        wr_ptr[i] = v;
        dinv[i] = rsqrtf((float)cnt[i] + 1.0f);
    }
    if (i == 0) row_start[n] = E;
}

__global__ void scatter_kernel(const int* __restrict__ src, const int* __restrict__ dst,
                               int* __restrict__ wr_ptr, int* __restrict__ csr_src, int E) {
    int e = blockIdx.x * blockDim.x + threadIdx.x;
    if (e < E) {
        int p = atomicAdd(&wr_ptr[dst[e]], 1);
        csr_src[p] = src[e];
    }
}

// ---------------- persistent tensor-core GEMM: g = bf16((in @ W) * dinv[row]) ----------------
// W staged in smem ONCE per block; block grid-strides over 64-row tiles.
#define WPAD 136

__device__ __forceinline__ void ldsm_x4(uint32_t* r, uint32_t addr) {
    asm volatile("ldmatrix.sync.aligned.m8n8.x4.shared.b16 {%0,%1,%2,%3}, [%4];"
                 : "=r"(r[0]), "=r"(r[1]), "=r"(r[2]), "=r"(r[3]) : "r"(addr));
}
__device__ __forceinline__ void ldsm_x4t(uint32_t* r, uint32_t addr) {
    asm volatile("ldmatrix.sync.aligned.m8n8.x4.trans.shared.b16 {%0,%1,%2,%3}, [%4];"
                 : "=r"(r[0]), "=r"(r[1]), "=r"(r[2]), "=r"(r[3]) : "r"(addr));
}
__device__ __forceinline__ void mma_bf16(float* c, const uint32_t* a, const uint32_t* b) {
    asm volatile("mma.sync.aligned.m16n8k16.row.col.f32.bf16.bf16.f32 "
                 "{%0,%1,%2,%3}, {%4,%5,%6,%7}, {%8,%9}, {%0,%1,%2,%3};"
                 : "+f"(c[0]), "+f"(c[1]), "+f"(c[2]), "+f"(c[3])
                 : "r"(a[0]), "r"(a[1]), "r"(a[2]), "r"(a[3]), "r"(b[0]), "r"(b[1]));
}

template <bool XF32>
__global__ void __launch_bounds__(256, 2)
gemm_kernel(const void* __restrict__ in,
            const __nv_bfloat16* __restrict__ WhiG,
            const __nv_bfloat16* __restrict__ WloG,
            const float* __restrict__ dinv, __nv_bfloat16* __restrict__ out,
            int n, int ntiles) {
    extern __shared__ __nv_bfloat16 sm[];
    __nv_bfloat16* Wh = sm;
    __nv_bfloat16* Wl = Wh + 128 * WPAD;
    __nv_bfloat16* Xh = Wl + 128 * WPAD;
    __nv_bfloat16* Xl = Xh + 64 * WPAD;   // used only when XF32

    int tid  = threadIdx.x;

    // stage pre-split W once per block
    {
        const uint4* src_h = (const uint4*)WhiG;
        const uint4* src_l = (const uint4*)WloG;
        #pragma unroll
        for (int i = tid; i < 2048; i += 256) {
            int r = i >> 4;
            int c = (i & 15) * 8;
            *(uint4*)(Wh + r * WPAD + c) = src_h[i];
            *(uint4*)(Wl + r * WPAD + c) = src_l[i];
        }
    }

    int wid  = tid >> 5;
    int lane = tid & 31;
    int wm = wid >> 2;
    int wn = wid & 3;
    int l7  = lane & 7;
    int lb3 = (lane >> 3) & 1;
    int lb4 = (lane >> 4) & 1;
    int quad = lane >> 2;
    int tcol = (lane & 3) * 2;

    for (int tile = blockIdx.x; tile < ntiles; tile += gridDim.x) {
        int row0 = tile * 64;

        if (XF32) {
            const float* inf = (const float*)in;
            #pragma unroll
            for (int i = tid; i < 64 * 32; i += 256) {
                int r = i >> 5, c = (i & 31) * 4;
                float4 v = make_float4(0.f, 0.f, 0.f, 0.f);
                if (row0 + r < n)
                    v = *(const float4*)(inf + (size_t)(row0 + r) * D + c);
                __nv_bfloat16 h0 = __float2bfloat16(v.x);
                __nv_bfloat16 h1 = __float2bfloat16(v.y);
                __nv_bfloat16 h2 = __float2bfloat16(v.z);
                __nv_bfloat16 h3 = __float2bfloat16(v.w);
                __nv_bfloat16* ph = Xh + r * WPAD + c;
                __nv_bfloat16* pl = Xl + r * WPAD + c;
                ph[0] = h0; ph[1] = h1; ph[2] = h2; ph[3] = h3;
                pl[0] = __float2bfloat16(v.x - __bfloat162float(h0));
                pl[1] = __float2bfloat16(v.y - __bfloat162float(h1));
                pl[2] = __float2bfloat16(v.z - __bfloat162float(h2));
                pl[3] = __float2bfloat16(v.w - __bfloat162float(h3));
            }
        } else {
            const __nv_bfloat16* inb = (const __nv_bfloat16*)in;
            #pragma unroll
            for (int i = tid; i < 64 * 16; i += 256) {
                int r = i >> 4, c = (i & 15) * 8;
                uint4 v = make_uint4(0u, 0u, 0u, 0u);
                if (row0 + r < n)
                    v = *(const uint4*)(inb + (size_t)(row0 + r) * D + c);
                *(uint4*)(Xh + r * WPAD + c) = v;
            }
        }
        __syncthreads();

        float acc[2][4][4];
        #pragma unroll
        for (int mt = 0; mt < 2; mt++)
            #pragma unroll
            for (int nt = 0; nt < 4; nt++)
                #pragma unroll
                for (int q = 0; q < 4; q++) acc[mt][nt][q] = 0.f;

        #pragma unroll
        for (int kk = 0; kk < 8; kk++) {
            int k0 = kk * 16;
            uint32_t ah[2][4], al[2][4];
            #pragma unroll
            for (int mt = 0; mt < 2; mt++) {
                int r = wm * 32 + mt * 16 + l7 + lb3 * 8;
                int c = k0 + lb4 * 8;
                ldsm_x4(ah[mt], (uint32_t)__cvta_generic_to_shared(Xh + r * WPAD + c));
                if (XF32)
                    ldsm_x4(al[mt], (uint32_t)__cvta_generic_to_shared(Xl + r * WPAD + c));
            }
            uint32_t bh[4][2], bl[4][2];
            #pragma unroll
            for (int p = 0; p < 2; p++) {
                int r = k0 + l7 + lb3 * 8;
                int c = wn * 32 + p * 16 + lb4 * 8;
                uint32_t t[4];
                ldsm_x4t(t, (uint32_t)__cvta_generic_to_shared(Wh + r * WPAD + c));
                bh[2*p][0] = t[0]; bh[2*p][1] = t[1]; bh[2*p+1][0] = t[2]; bh[2*p+1][1] = t[3];
                ldsm_x4t(t, (uint32_t)__cvta_generic_to_shared(Wl + r * WPAD + c));
                bl[2*p][0] = t[0]; bl[2*p][1] = t[1]; bl[2*p+1][0] = t[2]; bl[2*p+1][1] = t[3];
            }
            #pragma unroll
            for (int mt = 0; mt < 2; mt++)
                #pragma unroll
                for (int nt = 0; nt < 4; nt++) {
                    mma_bf16(acc[mt][nt], ah[mt], bh[nt]);
                    mma_bf16(acc[mt][nt], ah[mt], bl[nt]);
                    if (XF32)
                        mma_bf16(acc[mt][nt], al[mt], bh[nt]);
                }
        }

        #pragma unroll
        for (int mt = 0; mt < 2; mt++) {
            int r_lo = row0 + wm * 32 + mt * 16 + quad;
            int r_hi = r_lo + 8;
            float s_lo = (r_lo < n) ? dinv[r_lo] : 0.f;
            float s_hi = (r_hi < n) ? dinv[r_hi] : 0.f;
            #pragma unroll
            for (int nt = 0; nt < 4; nt++) {
                int c = wn * 32 + nt * 8 + tcol;
                if (r_lo < n) {
                    __nv_bfloat162 p = __floats2bfloat162_rn(acc[mt][nt][0] * s_lo,
                                                             acc[mt][nt][1] * s_lo);
                    *(uint32_t*)(out + (size_t)r_lo * D + c) = *(uint32_t*)&p;
                }
                if (r_hi < n) {
                    __nv_bfloat162 p = __floats2bfloat162_rn(acc[mt][nt][2] * s_hi,
                                                             acc[mt][nt][3] * s_hi);
                    *(uint32_t*)(out + (size_t)r_hi * D + c) = *(uint32_t*)&p;
                }
            }
        }
        __syncthreads();   // all ldsm reads done before next tile restages X
    }
}

// ---------------- fused CSR aggregate + post (bf16 h in/out) ----------------
__device__ __forceinline__ void acc_bf16x8(float* a, uint4 q) {
    __nv_bfloat162 b0 = *(__nv_bfloat162*)&q.x;
    __nv_bfloat162 b1 = *(__nv_bfloat162*)&q.y;
    __nv_bfloat162 b2 = *(__nv_bfloat162*)&q.z;
    __nv_bfloat162 b3 = *(__nv_bfloat162*)&q.w;
    float2 f0 = __bfloat1622float2(b0);
    float2 f1 = __bfloat1622float2(b1);
    float2 f2 = __bfloat1622float2(b2);
    float2 f3 = __bfloat1622float2(b3);
    a[0] += f0.x; a[1] += f0.y; a[2] += f1.x; a[3] += f1.y;
    a[4] += f2.x; a[5] += f2.y; a[6] += f3.x; a[7] += f3.y;
}

__global__ void __launch_bounds__(256)
agg_post_kernel(const __nv_bfloat16* __restrict__ g,
                const int* __restrict__ csr_src, const int* __restrict__ row_start,
                const __nv_bfloat16* __restrict__ resid,
                const float* __restrict__ dinv,
                const float* __restrict__ bias,
                const float* __restrict__ gamma,
                const float* __restrict__ beta,
                __nv_bfloat16* __restrict__ h_out,
                const int* __restrict__ batch,
                float* __restrict__ pooled,
                int n, int do_relu, int do_pool) {
    int warp = (blockIdx.x * blockDim.x + threadIdx.x) >> 5;
    int lane = threadIdx.x & 31;
    if (warp >= n) return;

    int half = lane >> 4;
    int hl   = lane & 15;
    int colb = hl * 8;

    int beg = row_start[warp];
    int cnt = row_start[warp + 1] - beg;

    float acc[8];
    #pragma unroll
    for (int k = 0; k < 8; k++) acc[k] = 0.f;

    if (half == 0) {   // self-loop term
        uint4 q = *(const uint4*)(g + (size_t)warp * D + colb);
        acc_bf16x8(acc, q);
    }

    for (int base = 0; base < cnt; base += 32) {
        int m = min(32, cnt - base);
        int idx = (base + lane < cnt) ? __ldg(&csr_src[beg + base + lane]) : 0;
        int j = 0;
        for (; j + 8 <= m; j += 8) {
            uint4 v[4];
            #pragma unroll
            for (int p = 0; p < 4; p++) {
                int s = __shfl_sync(0xffffffffu, idx, j + 2 * p + half);
                v[p] = *(const uint4*)(g + (size_t)s * D + colb);
            }
            #pragma unroll
            for (int p = 0; p < 4; p++) acc_bf16x8(acc, v[p]);
        }
        for (; j + 2 <= m; j += 2) {
            int s = __shfl_sync(0xffffffffu, idx, j + half);
            uint4 v = *(const uint4*)(g + (size_t)s * D + colb);
            acc_bf16x8(acc, v);
        }
        if (j < m) {
            int s = __shfl_sync(0xffffffffu, idx, j);
            if (half == 0) {
                uint4 v = *(const uint4*)(g + (size_t)s * D + colb);
                acc_bf16x8(acc, v);
            }
        }
    }

    #pragma unroll
    for (int k = 0; k < 8; k++)
        acc[k] += __shfl_xor_sync(0xffffffffu, acc[k], 16);

    float sc = dinv[warp];
    float t[8];
    {
        float4 b0 = *(const float4*)(bias + colb);
        float4 b1 = *(const float4*)(bias + colb + 4);
        t[0] = acc[0] * sc + b0.x; t[1] = acc[1] * sc + b0.y;
        t[2] = acc[2] * sc + b0.z; t[3] = acc[3] * sc + b0.w;
        t[4] = acc[4] * sc + b1.x; t[5] = acc[5] * sc + b1.y;
        t[6] = acc[6] * sc + b1.z; t[7] = acc[7] * sc + b1.w;
    }

    float sum = 0.f;
    #pragma unroll
    for (int k = 0; k < 8; k++) sum += t[k];
    #pragma unroll
    for (int o = 16; o > 0; o >>= 1) sum += __shfl_xor_sync(0xffffffffu, sum, o);
    float mu = sum * (1.0f / (2 * D));

    float ss = 0.f;
    #pragma unroll
    for (int k = 0; k < 8; k++) { t[k] -= mu; ss += t[k] * t[k]; }
    #pragma unroll
    for (int o = 16; o > 0; o >>= 1) ss += __shfl_xor_sync(0xffffffffu, ss, o);
    float inv = rsqrtf(ss * (1.0f / (2 * D)) + LN_EPS);

    float y[8];
    {
        float4 g0 = *(const float4*)(gamma + colb);
        float4 g1 = *(const float4*)(gamma + colb + 4);
        float4 e0 = *(const float4*)(beta + colb);
        float4 e1 = *(const float4*)(beta + colb + 4);
        y[0] = t[0] * inv * g0.x + e0.x; y[1] = t[1] * inv * g0.y + e0.y;
        y[2] = t[2] * inv * g0.z + e0.z; y[3] = t[3] * inv * g0.w + e0.w;
        y[4] = t[4] * inv * g1.x + e1.x; y[5] = t[5] * inv * g1.y + e1.y;
        y[6] = t[6] * inv * g1.z + e1.z; y[7] = t[7] * inv * g1.w + e1.w;
    }

    if (resid) {
        uint4 r = *(const uint4*)(resid + (size_t)warp * D + colb);
        float racc[8] = {0, 0, 0, 0, 0, 0, 0, 0};
        acc_bf16x8(racc, r);
        #pragma unroll
        for (int k = 0; k < 8; k++) y[k] += racc[k];
    }
    if (do_relu) {
        #pragma unroll
        for (int k = 0; k < 8; k++) y[k] = fmaxf(y[k], 0.f);
    }

    if (half == 0) {
        if (do_pool) {
            int b = batch[warp];
            float* p = pooled + (size_t)b * D + colb;
            asm volatile("red.global.add.v4.f32 [%0], {%1,%2,%3,%4};"
                         :: "l"(p), "f"(y[0]), "f"(y[1]), "f"(y[2]), "f"(y[3]) : "memory");
            asm volatile("red.global.add.v4.f32 [%0], {%1,%2,%3,%4};"
                         :: "l"(p + 4), "f"(y[4]), "f"(y[5]), "f"(y[6]), "f"(y[7]) : "memory");
        } else {
            __nv_bfloat162 p0 = __floats2bfloat162_rn(y[0], y[1]);
            __nv_bfloat162 p1 = __floats2bfloat162_rn(y[2], y[3]);
            __nv_bfloat162 p2 = __floats2bfloat162_rn(y[4], y[5]);
            __nv_bfloat162 p3 = __floats2bfloat162_rn(y[6], y[7]);
            uint4 o;
            o.x = *(uint32_t*)&p0; o.y = *(uint32_t*)&p1;
            o.z = *(uint32_t*)&p2; o.w = *(uint32_t*)&p3;
            *(uint4*)(h_out + (size_t)warp * D + colb) = o;
        }
    }
}

// ---------------- final readout ----------------
__global__ void out_kernel(const float* __restrict__ pooled, const float* __restrict__ gcnt,
                           const float* __restrict__ lin_w, const float* __restrict__ lin_b,
                           float* __restrict__ out, int ngraphs) {
    int warp = (blockIdx.x * blockDim.x + threadIdx.x) >> 5;
    int lane = threadIdx.x & 31;
    if (warp >= ngraphs) return;
    float acc = 0.f;
    #pragma unroll
    for (int q = 0; q < 4; q++) {
        int j = lane + 32 * q;
        acc += pooled[(size_t)warp * D + j] * lin_w[j];
    }
    #pragma unroll
    for (int o = 16; o > 0; o >>= 1) acc += __shfl_xor_sync(0xffffffffu, acc, o);
    if (lane == 0)
        out[warp] = acc / fmaxf(gcnt[warp], 1.0f) + lin_b[0];
}

// ---------------- host launcher ----------------
extern "C" void kernel_launch(void* const* d_in, const int* in_sizes, int n_in,
                              void* d_out, int out_size) {
    const float* x      = (const float*)d_in[0];
    const void*  ei     = d_in[1];
    const void*  batch  = d_in[2];
    const float* Ws     = (const float*)d_in[3];
    const float* bs     = (const float*)d_in[4];
    const float* gammas = (const float*)d_in[5];
    const float* betas  = (const float*)d_in[6];
    const float* lin_w  = (const float*)d_in[7];
    const float* lin_b  = (const float*)d_in[8];
    float* out = (float*)d_out;

    int n = in_sizes[2];
    int E = in_sizes[1] / 2;
    int ngraphs = out_size;
    if (n > NMAX) n = NMAX;
    if (E > EMAX) E = EMAX;

    __nv_bfloat16 *bufG, *bufA, *bufB, *Whi, *Wlo;
    float *dinv, *pooled, *gcnt;
    int *src, *dst, *csr_src, *cnt_int, *row_start, *wr_ptr, *blockSums, *batch32;
    cudaGetSymbolAddress((void**)&bufG,      d_bufG);
    cudaGetSymbolAddress((void**)&Whi,       d_Whi);
    cudaGetSymbolAddress((void**)&Wlo,       d_Wlo);
    cudaGetSymbolAddress((void**)&bufA,      d_bufA);
    cudaGetSymbolAddress((void**)&bufB,      d_bufB);
    cudaGetSymbolAddress((void**)&dinv,      d_dinv);
    cudaGetSymbolAddress((void**)&src,       d_src);
    cudaGetSymbolAddress((void**)&dst,       d_dst);
    cudaGetSymbolAddress((void**)&csr_src,   d_csr_src);
    cudaGetSymbolAddress((void**)&cnt_int,   d_cnt_int);
    cudaGetSymbolAddress((void**)&row_start, d_row_start);
    cudaGetSymbolAddress((void**)&wr_ptr,    d_wr_ptr);
    cudaGetSymbolAddress((void**)&blockSums, d_blockSums);
    cudaGetSymbolAddress((void**)&batch32,   d_batch32);
    cudaGetSymbolAddress((void**)&pooled,    d_pooled);
    cudaGetSymbolAddress((void**)&gcnt,      d_gcnt);

    const int smem_bytes = (2 * 128 * WPAD + 2 * 64 * WPAD) * sizeof(__nv_bfloat16);
    cudaFuncSetAttribute(gemm_kernel<true>, cudaFuncAttributeMaxDynamicSharedMemorySize, smem_bytes);
    cudaFuncSetAttribute(gemm_kernel<false>, cudaFuncAttributeMaxDynamicSharedMemorySize, smem_bytes);

    // ---- preamble ----
    detect_kernel<<<1, 32>>>((const int*)ei);
    cudaMemsetAsync(cnt_int, 0, (size_t)n * sizeof(int));
    cudaMemsetAsync(gcnt, 0, (size_t)ngraphs * sizeof(float));
    cudaMemsetAsync(pooled, 0, (size_t)ngraphs * D * sizeof(float));

    wsplit_kernel<<<(NLAYER * D * D + 255) / 256, 256>>>(Ws, Whi, Wlo);
    cvt_hist_kernel<<<(E + 255) / 256, 256>>>(ei, src, dst, cnt_int, E, n);
    cvt_batch_kernel<<<(n + 255) / 256, 256>>>(batch, batch32, gcnt, n);

    int nb = (n + SCAN_BLOCK - 1) / SCAN_BLOCK;
    scanA_kernel<<<nb, SCAN_TPB>>>(cnt_int, row_start, blockSums, n);
    scanB_kernel<<<1, SCAN_MAXBLOCKS>>>(blockSums, nb);
    scanC_kernel<<<(n + 255) / 256, 256>>>(row_start, blockSums, wr_ptr, cnt_int, dinv, n, E);
    scatter_kernel<<<(E + 255) / 256, 256>>>(src, dst, wr_ptr, csr_src, E);

    // ---- layers ----
    int ntiles = (n + 63) / 64;
    int gemm_grid = (ntiles < GEMM_GRID) ? ntiles : GEMM_GRID;
    int row_warp_blocks = (n + 7) / 8;
    const void* in_ptr = x;
    __nv_bfloat16* hbufs[2] = {bufA, bufB};
    for (int l = 0; l < 4; l++) {
        if (l == 0)
            gemm_kernel<true><<<gemm_grid, 256, smem_bytes>>>(in_ptr, Whi, Wlo, dinv, bufG, n, ntiles);
        else
            gemm_kernel<false><<<gemm_grid, 256, smem_bytes>>>(in_ptr, Whi + (size_t)l * D * D,
                                                               Wlo + (size_t)l * D * D, dinv, bufG, n, ntiles);
        __nv_bfloat16* h_out = hbufs[l & 1];
        int do_pool = (l == 3);
        agg_post_kernel<<<row_warp_blocks, 256>>>(bufG, csr_src, row_start,
                                                  (l == 0) ? nullptr : (const __nv_bfloat16*)in_ptr,
                                                  dinv,
                                                  bs + l * D, gammas + l * D, betas + l * D,
                                                  h_out, batch32, pooled,
                                                  n, (l < 3) ? 1 : 0, do_pool);
        in_ptr = h_out;
    }

    out_kernel<<<(ngraphs * 32 + 255) / 256, 256>>>(pooled, gcnt, lin_w, lin_b, out, ngraphs);
}

// round 11
// speedup vs baseline: 1.3313x; 1.0018x over previous
#include <cuda_runtime.h>
#include <cuda_bf16.h>
#include <stdint.h>

#define D 128
#define NMAX 100000
#define EMAX 1600000
#define NGRAPH 512
#define NLAYER 4
#define LN_EPS 1e-5f

#define SCAN_TPB 256
#define SCAN_ITEMS 8
#define SCAN_BLOCK (SCAN_TPB * SCAN_ITEMS)   // 2048
#define SCAN_MAXBLOCKS 1024

#define GEMM_GRID 296   // 2 blocks per SM (148 SMs)

// ---------------- scratch (no allocs allowed) ----------------
__device__ __nv_bfloat16 d_bufG[(size_t)NMAX * D];   // g = (in @ W) * dinv[row], bf16
__device__ __nv_bfloat16 d_bufA[(size_t)NMAX * D];   // h buffers, bf16
__device__ __nv_bfloat16 d_bufB[(size_t)NMAX * D];
__device__ __nv_bfloat16 d_Whi[NLAYER * D * D];
__device__ __nv_bfloat16 d_Wlo[NLAYER * D * D];
__device__ float d_dinv[NMAX];
__device__ int   d_src[EMAX];
__device__ int   d_dst[EMAX];
__device__ int   d_csr_src[EMAX];
__device__ int   d_cnt_int[NMAX];
__device__ int   d_row_start[NMAX + 1];
__device__ int   d_wr_ptr[NMAX];
__device__ int   d_blockSums[SCAN_MAXBLOCKS];
__device__ int   d_batch32[NMAX];
__device__ float d_pooled[NGRAPH * D];
__device__ float d_gcnt[NGRAPH];
__device__ int   d_is64;

// ---------------- dtype detection: int64 vs int32 indices ----------------
__global__ void detect_kernel(const int* __restrict__ w) {
    if (threadIdx.x == 0 && blockIdx.x == 0) {
        int zeros = 0;
        #pragma unroll
        for (int k = 0; k < 64; k++)
            if (w[2 * k + 1] == 0) zeros++;
        d_is64 = (zeros == 64) ? 1 : 0;
    }
}

// ---------------- W hi/lo split (once for all layers) ----------------
__global__ void wsplit_kernel(const float* __restrict__ Ws,
                              __nv_bfloat16* __restrict__ Whi,
                              __nv_bfloat16* __restrict__ Wlo) {
    int i = blockIdx.x * blockDim.x + threadIdx.x;
    if (i >= NLAYER * D * D) return;
    float w = Ws[i];
    __nv_bfloat16 h = __float2bfloat16(w);
    Whi[i] = h;
    Wlo[i] = __float2bfloat16(w - __bfloat162float(h));
}

// ---------------- fused: convert edges + degree histogram ----------------
__global__ void cvt_hist_kernel(const void* __restrict__ ei,
                                int* __restrict__ src, int* __restrict__ dst,
                                int* __restrict__ cnt, int E, int n) {
    int i = blockIdx.x * blockDim.x + threadIdx.x;
    if (i >= E) return;
    int s, d2;
    if (d_is64) {
        const long long* p = (const long long*)ei;
        s  = (int)p[i];
        d2 = (int)p[(size_t)E + i];
    } else {
        const int* p = (const int*)ei;
        s  = p[i];
        d2 = p[E + i];
    }
    s  = min(max(s, 0), n - 1);
    d2 = min(max(d2, 0), n - 1);
    src[i] = s;
    dst[i] = d2;
    atomicAdd(&cnt[d2], 1);
}

// ---------------- convert batch + graph counts (smem-aggregated) ----------------
__global__ void cvt_batch_kernel(const void* __restrict__ b,
                                 int* __restrict__ outb,
                                 float* __restrict__ gcnt, int n) {
    __shared__ int hist[NGRAPH];
    for (int k = threadIdx.x; k < NGRAPH; k += blockDim.x) hist[k] = 0;
    __syncthreads();
    int i = blockIdx.x * blockDim.x + threadIdx.x;
    if (i < n) {
        int v;
        if (d_is64) v = (int)((const long long*)b)[i];
        else        v = ((const int*)b)[i];
        v = min(max(v, 0), NGRAPH - 1);
        outb[i] = v;
        atomicAdd(&hist[v], 1);
    }
    __syncthreads();
    for (int k = threadIdx.x; k < NGRAPH; k += blockDim.x) {
        int c = hist[k];
        if (c) atomicAdd(&gcnt[k], (float)c);
    }
}

// ---------------- exclusive scan (3 kernels) ----------------
__global__ void scanA_kernel(const int* __restrict__ cnt, int* __restrict__ row_start,
                             int* __restrict__ blockSums, int n) {
    __shared__ int ssum[SCAN_TPB];
    int b = blockIdx.x, t = threadIdx.x;
    int base = b * SCAN_BLOCK + t * SCAN_ITEMS;
    int v[SCAN_ITEMS];
    int s = 0;
    #pragma unroll
    for (int i = 0; i < SCAN_ITEMS; i++) {
        v[i] = (base + i < n) ? cnt[base + i] : 0;
        s += v[i];
    }
    ssum[t] = s;
    __syncthreads();
    for (int off = 1; off < SCAN_TPB; off <<= 1) {
        int x = (t >= off) ? ssum[t - off] : 0;
        __syncthreads();
        ssum[t] += x;
        __syncthreads();
    }
    int run = ssum[t] - s;
    #pragma unroll
    for (int i = 0; i < SCAN_ITEMS; i++) {
        if (base + i < n) row_start[base + i] = run;
        run += v[i];
    }
    if (t == SCAN_TPB - 1) blockSums[b] = ssum[t];
}

__global__ void scanB_kernel(int* __restrict__ blockSums, int nb) {
    __shared__ int ssum[SCAN_MAXBLOCKS];
    int t = threadIdx.x;
    int v = (t < nb) ? blockSums[t] : 0;
    ssum[t] = v;
    __syncthreads();
    for (int off = 1; off < SCAN_MAXBLOCKS; off <<= 1) {
        int x = (t >= off) ? ssum[t - off] : 0;
        __syncthreads();
        ssum[t] += x;
        __syncthreads();
    }
    if (t < nb) blockSums[t] = ssum[t] - v;
}

__global__ void scanC_kernel(int* __restrict__ row_start, const int* __restrict__ blockSums,
                             int* __restrict__ wr_ptr, const int* __restrict__ cnt,
                             float* __restrict__ dinv, int n, int E) {
    int i = blockIdx.x * blockDim.x + threadIdx.x;
    if (i < n) {
        int v = row_start[i] + blockSums[i / SCAN_BLOCK];
        row_start[i] = v;
        wr_ptr[i] = v;
        dinv[i] = rsqrtf((float)cnt[i] + 1.0f);
    }
    if (i == 0) row_start[n] = E;
}

__global__ void scatter_kernel(const int* __restrict__ src, const int* __restrict__ dst,
                               int* __restrict__ wr_ptr, int* __restrict__ csr_src, int E) {
    int e = blockIdx.x * blockDim.x + threadIdx.x;
    if (e < E) {
        int p = atomicAdd(&wr_ptr[dst[e]], 1);
        csr_src[p] = src[e];
    }
}

// ---------------- persistent tensor-core GEMM: g = bf16((in @ W) * dinv[row]) ----------------
#define WPAD 136

__device__ __forceinline__ void ldsm_x4(uint32_t* r, uint32_t addr) {
    asm volatile("ldmatrix.sync.aligned.m8n8.x4.shared.b16 {%0,%1,%2,%3}, [%4];"
                 : "=r"(r[0]), "=r"(r[1]), "=r"(r[2]), "=r"(r[3]) : "r"(addr));
}
__device__ __forceinline__ void ldsm_x4t(uint32_t* r, uint32_t addr) {
    asm volatile("ldmatrix.sync.aligned.m8n8.x4.trans.shared.b16 {%0,%1,%2,%3}, [%4];"
                 : "=r"(r[0]), "=r"(r[1]), "=r"(r[2]), "=r"(r[3]) : "r"(addr));
}
__device__ __forceinline__ void mma_bf16(float* c, const uint32_t* a, const uint32_t* b) {
    asm volatile("mma.sync.aligned.m16n8k16.row.col.f32.bf16.bf16.f32 "
                 "{%0,%1,%2,%3}, {%4,%5,%6,%7}, {%8,%9}, {%0,%1,%2,%3};"
                 : "+f"(c[0]), "+f"(c[1]), "+f"(c[2]), "+f"(c[3])
                 : "r"(a[0]), "r"(a[1]), "r"(a[2]), "r"(a[3]), "r"(b[0]), "r"(b[1]));
}

template <bool XF32>
__global__ void __launch_bounds__(256, 2)
gemm_kernel(const void* __restrict__ in,
            const __nv_bfloat16* __restrict__ WhiG,
            const __nv_bfloat16* __restrict__ WloG,
            const float* __restrict__ dinv, __nv_bfloat16* __restrict__ out,
            int n, int ntiles) {
    extern __shared__ __nv_bfloat16 sm[];
    __nv_bfloat16* Wh = sm;
    __nv_bfloat16* Wl = Wh + 128 * WPAD;
    __nv_bfloat16* Xh = Wl + 128 * WPAD;
    __nv_bfloat16* Xl = Xh + 64 * WPAD;   // used only when XF32

    int tid  = threadIdx.x;

    // stage pre-split W once per block
    {
        const uint4* src_h = (const uint4*)WhiG;
        const uint4* src_l = (const uint4*)WloG;
        #pragma unroll
        for (int i = tid; i < 2048; i += 256) {
            int r = i >> 4;
            int c = (i & 15) * 8;
            *(uint4*)(Wh + r * WPAD + c) = src_h[i];
            *(uint4*)(Wl + r * WPAD + c) = src_l[i];
        }
    }

    int wid  = tid >> 5;
    int lane = tid & 31;
    int wm = wid >> 2;
    int wn = wid & 3;
    int l7  = lane & 7;
    int lb3 = (lane >> 3) & 1;
    int lb4 = (lane >> 4) & 1;
    int quad = lane >> 2;
    int tcol = (lane & 3) * 2;

    for (int tile = blockIdx.x; tile < ntiles; tile += gridDim.x) {
        int row0 = tile * 64;

        if (XF32) {
            const float* inf = (const float*)in;
            #pragma unroll
            for (int i = tid; i < 64 * 32; i += 256) {
                int r = i >> 5, c = (i & 31) * 4;
                float4 v = make_float4(0.f, 0.f, 0.f, 0.f);
                if (row0 + r < n)
                    v = *(const float4*)(inf + (size_t)(row0 + r) * D + c);
                __nv_bfloat16 h0 = __float2bfloat16(v.x);
                __nv_bfloat16 h1 = __float2bfloat16(v.y);
                __nv_bfloat16 h2 = __float2bfloat16(v.z);
                __nv_bfloat16 h3 = __float2bfloat16(v.w);
                __nv_bfloat16* ph = Xh + r * WPAD + c;
                __nv_bfloat16* pl = Xl + r * WPAD + c;
                ph[0] = h0; ph[1] = h1; ph[2] = h2; ph[3] = h3;
                pl[0] = __float2bfloat16(v.x - __bfloat162float(h0));
                pl[1] = __float2bfloat16(v.y - __bfloat162float(h1));
                pl[2] = __float2bfloat16(v.z - __bfloat162float(h2));
                pl[3] = __float2bfloat16(v.w - __bfloat162float(h3));
            }
        } else {
            const __nv_bfloat16* inb = (const __nv_bfloat16*)in;
            #pragma unroll
            for (int i = tid; i < 64 * 16; i += 256) {
                int r = i >> 4, c = (i & 15) * 8;
                uint4 v = make_uint4(0u, 0u, 0u, 0u);
                if (row0 + r < n)
                    v = *(const uint4*)(inb + (size_t)(row0 + r) * D + c);
                *(uint4*)(Xh + r * WPAD + c) = v;
            }
        }
        __syncthreads();

        float acc[2][4][4];
        #pragma unroll
        for (int mt = 0; mt < 2; mt++)
            #pragma unroll
            for (int nt = 0; nt < 4; nt++)
                #pragma unroll
                for (int q = 0; q < 4; q++) acc[mt][nt][q] = 0.f;

        #pragma unroll
        for (int kk = 0; kk < 8; kk++) {
            int k0 = kk * 16;
            uint32_t ah[2][4], al[2][4];
            #pragma unroll
            for (int mt = 0; mt < 2; mt++) {
                int r = wm * 32 + mt * 16 + l7 + lb3 * 8;
                int c = k0 + lb4 * 8;
                ldsm_x4(ah[mt], (uint32_t)__cvta_generic_to_shared(Xh + r * WPAD + c));
                if (XF32)
                    ldsm_x4(al[mt], (uint32_t)__cvta_generic_to_shared(Xl + r * WPAD + c));
            }
            uint32_t bh[4][2], bl[4][2];
            #pragma unroll
            for (int p = 0; p < 2; p++) {
                int r = k0 + l7 + lb3 * 8;
                int c = wn * 32 + p * 16 + lb4 * 8;
                uint32_t t[4];
                ldsm_x4t(t, (uint32_t)__cvta_generic_to_shared(Wh + r * WPAD + c));
                bh[2*p][0] = t[0]; bh[2*p][1] = t[1]; bh[2*p+1][0] = t[2]; bh[2*p+1][1] = t[3];
                ldsm_x4t(t, (uint32_t)__cvta_generic_to_shared(Wl + r * WPAD + c));
                bl[2*p][0] = t[0]; bl[2*p][1] = t[1]; bl[2*p+1][0] = t[2]; bl[2*p+1][1] = t[3];
            }
            #pragma unroll
            for (int mt = 0; mt < 2; mt++)
                #pragma unroll
                for (int nt = 0; nt < 4; nt++) {
                    mma_bf16(acc[mt][nt], ah[mt], bh[nt]);
                    mma_bf16(acc[mt][nt], ah[mt], bl[nt]);
                    if (XF32)
                        mma_bf16(acc[mt][nt], al[mt], bh[nt]);
                }
        }

        #pragma unroll
        for (int mt = 0; mt < 2; mt++) {
            int r_lo = row0 + wm * 32 + mt * 16 + quad;
            int r_hi = r_lo + 8;
            float s_lo = (r_lo < n) ? dinv[r_lo] : 0.f;
            float s_hi = (r_hi < n) ? dinv[r_hi] : 0.f;
            #pragma unroll
            for (int nt = 0; nt < 4; nt++) {
                int c = wn * 32 + nt * 8 + tcol;
                if (r_lo < n) {
                    __nv_bfloat162 p = __floats2bfloat162_rn(acc[mt][nt][0] * s_lo,
                                                             acc[mt][nt][1] * s_lo);
                    *(uint32_t*)(out + (size_t)r_lo * D + c) = *(uint32_t*)&p;
                }
                if (r_hi < n) {
                    __nv_bfloat162 p = __floats2bfloat162_rn(acc[mt][nt][2] * s_hi,
                                                             acc[mt][nt][3] * s_hi);
                    *(uint32_t*)(out + (size_t)r_hi * D + c) = *(uint32_t*)&p;
                }
            }
        }
        __syncthreads();   // all ldsm reads done before next tile restages X
    }
}

// ---------------- fused CSR aggregate + post (bf16 h in/out) ----------------
// warp per dst row; half-warp per edge; ALWAYS 4 loads in flight per lane,
// invalid pairs masked by fma weight 0 (loads a safe row instead).
__device__ __forceinline__ void acc_bf16x8_w(float* a, uint4 q, float w) {
    __nv_bfloat162 b0 = *(__nv_bfloat162*)&q.x;
    __nv_bfloat162 b1 = *(__nv_bfloat162*)&q.y;
    __nv_bfloat162 b2 = *(__nv_bfloat162*)&q.z;
    __nv_bfloat162 b3 = *(__nv_bfloat162*)&q.w;
    float2 f0 = __bfloat1622float2(b0);
    float2 f1 = __bfloat1622float2(b1);
    float2 f2 = __bfloat1622float2(b2);
    float2 f3 = __bfloat1622float2(b3);
    a[0] = fmaf(f0.x, w, a[0]); a[1] = fmaf(f0.y, w, a[1]);
    a[2] = fmaf(f1.x, w, a[2]); a[3] = fmaf(f1.y, w, a[3]);
    a[4] = fmaf(f2.x, w, a[4]); a[5] = fmaf(f2.y, w, a[5]);
    a[6] = fmaf(f3.x, w, a[6]); a[7] = fmaf(f3.y, w, a[7]);
}

__global__ void __launch_bounds__(256)
agg_post_kernel(const __nv_bfloat16* __restrict__ g,
                const int* __restrict__ csr_src, const int* __restrict__ row_start,
                const __nv_bfloat16* __restrict__ resid,
                const float* __restrict__ dinv,
                const float* __restrict__ bias,
                const float* __restrict__ gamma,
                const float* __restrict__ beta,
                __nv_bfloat16* __restrict__ h_out,
                const int* __restrict__ batch,
                float* __restrict__ pooled,
                int n, int do_relu, int do_pool) {
    int warp = (blockIdx.x * blockDim.x + threadIdx.x) >> 5;
    int lane = threadIdx.x & 31;
    if (warp >= n) return;

    int half = lane >> 4;
    int hl   = lane & 15;
    int colb = hl * 8;

    int beg = row_start[warp];
    int cnt = row_start[warp + 1] - beg;

    float acc[8];
    #pragma unroll
    for (int k = 0; k < 8; k++) acc[k] = 0.f;

    if (half == 0) {   // self-loop term
        uint4 q = *(const uint4*)(g + (size_t)warp * D + colb);
        acc_bf16x8_w(acc, q, 1.0f);
    }

    for (int base = 0; base < cnt; base += 32) {
        int m = min(32, cnt - base);
        // lanes past the end default to this warp's own (valid) row; masked by w=0
        int idx = (base + lane < cnt) ? __ldg(&csr_src[beg + base + lane]) : warp;
        for (int j = 0; j < m; j += 8) {
            uint4 v[4];
            float w[4];
            #pragma unroll
            for (int p = 0; p < 4; p++) {
                int k = j + 2 * p + half;
                int s = __shfl_sync(0xffffffffu, idx, k);  // k>=32 wraps to valid lane
                w[p] = (k < m) ? 1.0f : 0.0f;
                v[p] = *(const uint4*)(g + (size_t)s * D + colb);
            }
            #pragma unroll
            for (int p = 0; p < 4; p++) acc_bf16x8_w(acc, v[p], w[p]);
        }
    }

    #pragma unroll
    for (int k = 0; k < 8; k++)
        acc[k] += __shfl_xor_sync(0xffffffffu, acc[k], 16);

    float sc = dinv[warp];
    float t[8];
    {
        float4 b0 = *(const float4*)(bias + colb);
        float4 b1 = *(const float4*)(bias + colb + 4);
        t[0] = acc[0] * sc + b0.x; t[1] = acc[1] * sc + b0.y;
        t[2] = acc[2] * sc + b0.z; t[3] = acc[3] * sc + b0.w;
        t[4] = acc[4] * sc + b1.x; t[5] = acc[5] * sc + b1.y;
        t[6] = acc[6] * sc + b1.z; t[7] = acc[7] * sc + b1.w;
    }

    float sum = 0.f;
    #pragma unroll
    for (int k = 0; k < 8; k++) sum += t[k];
    #pragma unroll
    for (int o = 16; o > 0; o >>= 1) sum += __shfl_xor_sync(0xffffffffu, sum, o);
    float mu = sum * (1.0f / (2 * D));

    float ss = 0.f;
    #pragma unroll
    for (int k = 0; k < 8; k++) { t[k] -= mu; ss += t[k] * t[k]; }
    #pragma unroll
    for (int o = 16; o > 0; o >>= 1) ss += __shfl_xor_sync(0xffffffffu, ss, o);
    float inv = rsqrtf(ss * (1.0f / (2 * D)) + LN_EPS);

    float y[8];
    {
        float4 g0 = *(const float4*)(gamma + colb);
        float4 g1 = *(const float4*)(gamma + colb + 4);
        float4 e0 = *(const float4*)(beta + colb);
        float4 e1 = *(const float4*)(beta + colb + 4);
        y[0] = t[0] * inv * g0.x + e0.x; y[1] = t[1] * inv * g0.y + e0.y;
        y[2] = t[2] * inv * g0.z + e0.z; y[3] = t[3] * inv * g0.w + e0.w;
        y[4] = t[4] * inv * g1.x + e1.x; y[5] = t[5] * inv * g1.y + e1.y;
        y[6] = t[6] * inv * g1.z + e1.z; y[7] = t[7] * inv * g1.w + e1.w;
    }

    if (resid) {
        uint4 r = *(const uint4*)(resid + (size_t)warp * D + colb);
        float racc[8] = {0, 0, 0, 0, 0, 0, 0, 0};
        acc_bf16x8_w(racc, r, 1.0f);
        #pragma unroll
        for (int k = 0; k < 8; k++) y[k] += racc[k];
    }
    if (do_relu) {
        #pragma unroll
        for (int k = 0; k < 8; k++) y[k] = fmaxf(y[k], 0.f);
    }

    if (half == 0) {
        if (do_pool) {
            int b = batch[warp];
            float* p = pooled + (size_t)b * D + colb;
            asm volatile("red.global.add.v4.f32 [%0], {%1,%2,%3,%4};"
                         :: "l"(p), "f"(y[0]), "f"(y[1]), "f"(y[2]), "f"(y[3]) : "memory");
            asm volatile("red.global.add.v4.f32 [%0], {%1,%2,%3,%4};"
                         :: "l"(p + 4), "f"(y[4]), "f"(y[5]), "f"(y[6]), "f"(y[7]) : "memory");
        } else {
            __nv_bfloat162 p0 = __floats2bfloat162_rn(y[0], y[1]);
            __nv_bfloat162 p1 = __floats2bfloat162_rn(y[2], y[3]);
            __nv_bfloat162 p2 = __floats2bfloat162_rn(y[4], y[5]);
            __nv_bfloat162 p3 = __floats2bfloat162_rn(y[6], y[7]);
            uint4 o;
            o.x = *(uint32_t*)&p0; o.y = *(uint32_t*)&p1;
            o.z = *(uint32_t*)&p2; o.w = *(uint32_t*)&p3;
            *(uint4*)(h_out + (size_t)warp * D + colb) = o;
        }
    }
}

// ---------------- final readout ----------------
__global__ void out_kernel(const float* __restrict__ pooled, const float* __restrict__ gcnt,
                           const float* __restrict__ lin_w, const float* __restrict__ lin_b,
                           float* __restrict__ out, int ngraphs) {
    int warp = (blockIdx.x * blockDim.x + threadIdx.x) >> 5;
    int lane = threadIdx.x & 31;
    if (warp >= ngraphs) return;
    float acc = 0.f;
    #pragma unroll
    for (int q = 0; q < 4; q++) {
        int j = lane + 32 * q;
        acc += pooled[(size_t)warp * D + j] * lin_w[j];
    }
    #pragma unroll
    for (int o = 16; o > 0; o >>= 1) acc += __shfl_xor_sync(0xffffffffu, acc, o);
    if (lane == 0)
        out[warp] = acc / fmaxf(gcnt[warp], 1.0f) + lin_b[0];
}

// ---------------- host launcher ----------------
extern "C" void kernel_launch(void* const* d_in, const int* in_sizes, int n_in,
                              void* d_out, int out_size) {
    const float* x      = (const float*)d_in[0];
    const void*  ei     = d_in[1];
    const void*  batch  = d_in[2];
    const float* Ws     = (const float*)d_in[3];
    const float* bs     = (const float*)d_in[4];
    const float* gammas = (const float*)d_in[5];
    const float* betas  = (const float*)d_in[6];
    const float* lin_w  = (const float*)d_in[7];
    const float* lin_b  = (const float*)d_in[8];
    float* out = (float*)d_out;

    int n = in_sizes[2];
    int E = in_sizes[1] / 2;
    int ngraphs = out_size;
    if (n > NMAX) n = NMAX;
    if (E > EMAX) E = EMAX;

    __nv_bfloat16 *bufG, *bufA, *bufB, *Whi, *Wlo;
    float *dinv, *pooled, *gcnt;
    int *src, *dst, *csr_src, *cnt_int, *row_start, *wr_ptr, *blockSums, *batch32;
    cudaGetSymbolAddress((void**)&bufG,      d_bufG);
    cudaGetSymbolAddress((void**)&Whi,       d_Whi);
    cudaGetSymbolAddress((void**)&Wlo,       d_Wlo);
    cudaGetSymbolAddress((void**)&bufA,      d_bufA);
    cudaGetSymbolAddress((void**)&bufB,      d_bufB);
    cudaGetSymbolAddress((void**)&dinv,      d_dinv);
    cudaGetSymbolAddress((void**)&src,       d_src);
    cudaGetSymbolAddress((void**)&dst,       d_dst);
    cudaGetSymbolAddress((void**)&csr_src,   d_csr_src);
    cudaGetSymbolAddress((void**)&cnt_int,   d_cnt_int);
    cudaGetSymbolAddress((void**)&row_start, d_row_start);
    cudaGetSymbolAddress((void**)&wr_ptr,    d_wr_ptr);
    cudaGetSymbolAddress((void**)&blockSums, d_blockSums);
    cudaGetSymbolAddress((void**)&batch32,   d_batch32);
    cudaGetSymbolAddress((void**)&pooled,    d_pooled);
    cudaGetSymbolAddress((void**)&gcnt,      d_gcnt);

    const int smem_bytes = (2 * 128 * WPAD + 2 * 64 * WPAD) * sizeof(__nv_bfloat16);
    cudaFuncSetAttribute(gemm_kernel<true>, cudaFuncAttributeMaxDynamicSharedMemorySize, smem_bytes);
    cudaFuncSetAttribute(gemm_kernel<false>, cudaFuncAttributeMaxDynamicSharedMemorySize, smem_bytes);

    // ---- preamble ----
    detect_kernel<<<1, 32>>>((const int*)ei);
    cudaMemsetAsync(cnt_int, 0, (size_t)n * sizeof(int));
    cudaMemsetAsync(gcnt, 0, (size_t)ngraphs * sizeof(float));
    cudaMemsetAsync(pooled, 0, (size_t)ngraphs * D * sizeof(float));

    wsplit_kernel<<<(NLAYER * D * D + 255) / 256, 256>>>(Ws, Whi, Wlo);
    cvt_hist_kernel<<<(E + 255) / 256, 256>>>(ei, src, dst, cnt_int, E, n);
    cvt_batch_kernel<<<(n + 255) / 256, 256>>>(batch, batch32, gcnt, n);

    int nb = (n + SCAN_BLOCK - 1) / SCAN_BLOCK;
    scanA_kernel<<<nb, SCAN_TPB>>>(cnt_int, row_start, blockSums, n);
    scanB_kernel<<<1, SCAN_MAXBLOCKS>>>(blockSums, nb);
    scanC_kernel<<<(n + 255) / 256, 256>>>(row_start, blockSums, wr_ptr, cnt_int, dinv, n, E);
    scatter_kernel<<<(E + 255) / 256, 256>>>(src, dst, wr_ptr, csr_src, E);

    // ---- layers ----
    int ntiles = (n + 63) / 64;
    int gemm_grid = (ntiles < GEMM_GRID) ? ntiles : GEMM_GRID;
    int row_warp_blocks = (n + 7) / 8;
    const void* in_ptr = x;
    __nv_bfloat16* hbufs[2] = {bufA, bufB};
    for (int l = 0; l < 4; l++) {
        if (l == 0)
            gemm_kernel<true><<<gemm_grid, 256, smem_bytes>>>(in_ptr, Whi, Wlo, dinv, bufG, n, ntiles);
        else
            gemm_kernel<false><<<gemm_grid, 256, smem_bytes>>>(in_ptr, Whi + (size_t)l * D * D,
                                                               Wlo + (size_t)l * D * D, dinv, bufG, n, ntiles);
        __nv_bfloat16* h_out = hbufs[l & 1];
        int do_pool = (l == 3);
        agg_post_kernel<<<row_warp_blocks, 256>>>(bufG, csr_src, row_start,
                                                  (l == 0) ? nullptr : (const __nv_bfloat16*)in_ptr,
                                                  dinv,
                                                  bs + l * D, gammas + l * D, betas + l * D,
                                                  h_out, batch32, pooled,
                                                  n, (l < 3) ? 1 : 0, do_pool);
        in_ptr = h_out;
    }

    out_kernel<<<(ngraphs * 32 + 255) / 256, 256>>>(pooled, gcnt, lin_w, lin_b, out, ngraphs);
}

// round 13
// speedup vs baseline: 1.3479x; 1.0125x over previous
#include <cuda_runtime.h>
#include <cuda_bf16.h>
#include <stdint.h>

#define D 128
#define NMAX 100000
#define EMAX 1600000
#define NGRAPH 512
#define NLAYER 4
#define LN_EPS 1e-5f

#define SCAN_TPB 256
#define SCAN_ITEMS 8
#define SCAN_BLOCK (SCAN_TPB * SCAN_ITEMS)   // 2048
#define SCAN_MAXBLOCKS 1024

#define GEMM_GRID 296   // 2 blocks per SM (148 SMs)

// ---------------- scratch (no allocs allowed) ----------------
__device__ __nv_bfloat16 d_bufG[(size_t)NMAX * D];   // g = (in @ W) * dinv[row], bf16
__device__ __nv_bfloat16 d_bufA[(size_t)NMAX * D];   // h buffers, bf16
__device__ __nv_bfloat16 d_bufB[(size_t)NMAX * D];
__device__ __nv_bfloat16 d_Whi[NLAYER * D * D];
__device__ __nv_bfloat16 d_Wlo[NLAYER * D * D];
__device__ float d_dinv[NMAX];
__device__ int   d_csr_src[EMAX];
__device__ int   d_cnt_int[NMAX];
__device__ int   d_row_start[NMAX + 1];
__device__ int   d_wr_ptr[NMAX];
__device__ int   d_blockSums[SCAN_MAXBLOCKS];
__device__ int   d_batch32[NMAX];
__device__ float d_pooled[NGRAPH * D];
__device__ float d_gcnt[NGRAPH];
__device__ int   d_is64;

// ---------------- dtype detection: int64 vs int32 indices ----------------
__global__ void detect_kernel(const int* __restrict__ w) {
    if (threadIdx.x == 0 && blockIdx.x == 0) {
        int zeros = 0;
        #pragma unroll
        for (int k = 0; k < 64; k++)
            if (w[2 * k + 1] == 0) zeros++;
        d_is64 = (zeros == 64) ? 1 : 0;
    }
}

// ---------------- W hi/lo split (once for all layers) ----------------
__global__ void wsplit_kernel(const float* __restrict__ Ws,
                              __nv_bfloat16* __restrict__ Whi,
                              __nv_bfloat16* __restrict__ Wlo) {
    int i = blockIdx.x * blockDim.x + threadIdx.x;
    if (i >= NLAYER * D * D) return;
    float w = Ws[i];
    __nv_bfloat16 h = __float2bfloat16(w);
    Whi[i] = h;
    Wlo[i] = __float2bfloat16(w - __bfloat162float(h));
}

// ---------------- helpers to read edge endpoints from raw buffer ----------------
__device__ __forceinline__ int edge_src(const void* ei, int i, int E, int n) {
    int s;
    if (d_is64) s = (int)((const long long*)ei)[i];
    else        s = ((const int*)ei)[i];
    return min(max(s, 0), n - 1);
}
__device__ __forceinline__ int edge_dst(const void* ei, int i, int E, int n) {
    int s;
    if (d_is64) s = (int)((const long long*)ei)[(size_t)E + i];
    else        s = ((const int*)ei)[E + i];
    return min(max(s, 0), n - 1);
}

// ---------------- degree histogram directly from raw edges ----------------
__global__ void hist_kernel(const void* __restrict__ ei,
                            int* __restrict__ cnt, int E, int n) {
    int i = blockIdx.x * blockDim.x + threadIdx.x;
    if (i >= E) return;
    atomicAdd(&cnt[edge_dst(ei, i, E, n)], 1);
}

// ---------------- convert batch + graph counts (smem-aggregated) ----------------
__global__ void cvt_batch_kernel(const void* __restrict__ b,
                                 int* __restrict__ outb,
                                 float* __restrict__ gcnt, int n) {
    __shared__ int hist[NGRAPH];
    for (int k = threadIdx.x; k < NGRAPH; k += blockDim.x) hist[k] = 0;
    __syncthreads();
    int i = blockIdx.x * blockDim.x + threadIdx.x;
    if (i < n) {
        int v;
        if (d_is64) v = (int)((const long long*)b)[i];
        else        v = ((const int*)b)[i];
        v = min(max(v, 0), NGRAPH - 1);
        outb[i] = v;
        atomicAdd(&hist[v], 1);
    }
    __syncthreads();
    for (int k = threadIdx.x; k < NGRAPH; k += blockDim.x) {
        int c = hist[k];
        if (c) atomicAdd(&gcnt[k], (float)c);
    }
}

// ---------------- exclusive scan (3 kernels) ----------------
__global__ void scanA_kernel(const int* __restrict__ cnt, int* __restrict__ row_start,
                             int* __restrict__ blockSums, int n) {
    __shared__ int ssum[SCAN_TPB];
    int b = blockIdx.x, t = threadIdx.x;
    int base = b * SCAN_BLOCK + t * SCAN_ITEMS;
    int v[SCAN_ITEMS];
    int s = 0;
    #pragma unroll
    for (int i = 0; i < SCAN_ITEMS; i++) {
        v[i] = (base + i < n) ? cnt[base + i] : 0;
        s += v[i];
    }
    ssum[t] = s;
    __syncthreads();
    for (int off = 1; off < SCAN_TPB; off <<= 1) {
        int x = (t >= off) ? ssum[t - off] : 0;
        __syncthreads();
        ssum[t] += x;
        __syncthreads();
    }
    int run = ssum[t] - s;
    #pragma unroll
    for (int i = 0; i < SCAN_ITEMS; i++) {
        if (base + i < n) row_start[base + i] = run;
        run += v[i];
    }
    if (t == SCAN_TPB - 1) blockSums[b] = ssum[t];
}

__global__ void scanB_kernel(int* __restrict__ blockSums, int nb) {
    __shared__ int ssum[SCAN_MAXBLOCKS];
    int t = threadIdx.x;
    int v = (t < nb) ? blockSums[t] : 0;
    ssum[t] = v;
    __syncthreads();
    for (int off = 1; off < SCAN_MAXBLOCKS; off <<= 1) {
        int x = (t >= off) ? ssum[t - off] : 0;
        __syncthreads();
        ssum[t] += x;
        __syncthreads();
    }
    if (t < nb) blockSums[t] = ssum[t] - v;
}

__global__ void scanC_kernel(int* __restrict__ row_start, const int* __restrict__ blockSums,
                             int* __restrict__ wr_ptr, const int* __restrict__ cnt,
                             float* __restrict__ dinv, int n, int E) {
    int i = blockIdx.x * blockDim.x + threadIdx.x;
    if (i < n) {
        int v = row_start[i] + blockSums[i / SCAN_BLOCK];
        row_start[i] = v;
        wr_ptr[i] = v;
        dinv[i] = rsqrtf((float)cnt[i] + 1.0f);
    }
    if (i == 0) row_start[n] = E;
}

// ---------------- scatter directly from raw edges ----------------
__global__ void scatter_kernel(const void* __restrict__ ei,
                               int* __restrict__ wr_ptr, int* __restrict__ csr_src,
                               int E, int n) {
    int e = blockIdx.x * blockDim.x + threadIdx.x;
    if (e < E) {
        int d2 = edge_dst(ei, e, E, n);
        int s  = edge_src(ei, e, E, n);
        int p = atomicAdd(&wr_ptr[d2], 1);
        csr_src[p] = s;
    }
}

// ---------------- persistent tensor-core GEMM: g = bf16((in @ W) * dinv[row]) ----------------
#define WPAD 136

__device__ __forceinline__ void ldsm_x4(uint32_t* r, uint32_t addr) {
    asm volatile("ldmatrix.sync.aligned.m8n8.x4.shared.b16 {%0,%1,%2,%3}, [%4];"
                 : "=r"(r[0]), "=r"(r[1]), "=r"(r[2]), "=r"(r[3]) : "r"(addr));
}
__device__ __forceinline__ void ldsm_x4t(uint32_t* r, uint32_t addr) {
    asm volatile("ldmatrix.sync.aligned.m8n8.x4.trans.shared.b16 {%0,%1,%2,%3}, [%4];"
                 : "=r"(r[0]), "=r"(r[1]), "=r"(r[2]), "=r"(r[3]) : "r"(addr));
}
__device__ __forceinline__ void mma_bf16(float* c, const uint32_t* a, const uint32_t* b) {
    asm volatile("mma.sync.aligned.m16n8k16.row.col.f32.bf16.bf16.f32 "
                 "{%0,%1,%2,%3}, {%4,%5,%6,%7}, {%8,%9}, {%0,%1,%2,%3};"
                 : "+f"(c[0]), "+f"(c[1]), "+f"(c[2]), "+f"(c[3])
                 : "r"(a[0]), "r"(a[1]), "r"(a[2]), "r"(a[3]), "r"(b[0]), "r"(b[1]));
}

template <bool XF32>
__global__ void __launch_bounds__(256, 2)
gemm_kernel(const void* __restrict__ in,
            const __nv_bfloat16* __restrict__ WhiG,
            const __nv_bfloat16* __restrict__ WloG,
            const float* __restrict__ dinv, __nv_bfloat16* __restrict__ out,
            int n, int ntiles) {
    extern __shared__ __nv_bfloat16 sm[];
    __nv_bfloat16* Wh = sm;
    __nv_bfloat16* Wl = Wh + 128 * WPAD;
    __nv_bfloat16* Xh = Wl + 128 * WPAD;
    __nv_bfloat16* Xl = Xh + 64 * WPAD;   // used only when XF32

    int tid  = threadIdx.x;

    // stage pre-split W once per block
    {
        const uint4* src_h = (const uint4*)WhiG;
        const uint4* src_l = (const uint4*)WloG;
        #pragma unroll
        for (int i = tid; i < 2048; i += 256) {
            int r = i >> 4;
            int c = (i & 15) * 8;
            *(uint4*)(Wh + r * WPAD + c) = src_h[i];
            *(uint4*)(Wl + r * WPAD + c) = src_l[i];
        }
    }

    int wid  = tid >> 5;
    int lane = tid & 31;
    int wm = wid >> 2;
    int wn = wid & 3;
    int l7  = lane & 7;
    int lb3 = (lane >> 3) & 1;
    int lb4 = (lane >> 4) & 1;
    int quad = lane >> 2;
    int tcol = (lane & 3) * 2;

    for (int tile = blockIdx.x; tile < ntiles; tile += gridDim.x) {
        int row0 = tile * 64;

        if (XF32) {
            const float* inf = (const float*)in;
            #pragma unroll
            for (int i = tid; i < 64 * 32; i += 256) {
                int r = i >> 5, c = (i & 31) * 4;
                float4 v = make_float4(0.f, 0.f, 0.f, 0.f);
                if (row0 + r < n)
                    v = *(const float4*)(inf + (size_t)(row0 + r) * D + c);
                __nv_bfloat16 h0 = __float2bfloat16(v.x);
                __nv_bfloat16 h1 = __float2bfloat16(v.y);
                __nv_bfloat16 h2 = __float2bfloat16(v.z);
                __nv_bfloat16 h3 = __float2bfloat16(v.w);
                __nv_bfloat16* ph = Xh + r * WPAD + c;
                __nv_bfloat16* pl = Xl + r * WPAD + c;
                ph[0] = h0; ph[1] = h1; ph[2] = h2; ph[3] = h3;
                pl[0] = __float2bfloat16(v.x - __bfloat162float(h0));
                pl[1] = __float2bfloat16(v.y - __bfloat162float(h1));
                pl[2] = __float2bfloat16(v.z - __bfloat162float(h2));
                pl[3] = __float2bfloat16(v.w - __bfloat162float(h3));
            }
        } else {
            const __nv_bfloat16* inb = (const __nv_bfloat16*)in;
            #pragma unroll
            for (int i = tid; i < 64 * 16; i += 256) {
                int r = i >> 4, c = (i & 15) * 8;
                uint4 v = make_uint4(0u, 0u, 0u, 0u);
                if (row0 + r < n)
                    v = *(const uint4*)(inb + (size_t)(row0 + r) * D + c);
                *(uint4*)(Xh + r * WPAD + c) = v;
            }
        }
        __syncthreads();

        float acc[2][4][4];
        #pragma unroll
        for (int mt = 0; mt < 2; mt++)
            #pragma unroll
            for (int nt = 0; nt < 4; nt++)
                #pragma unroll
                for (int q = 0; q < 4; q++) acc[mt][nt][q] = 0.f;

        #pragma unroll
        for (int kk = 0; kk < 8; kk++) {
            int k0 = kk * 16;
            uint32_t ah[2][4], al[2][4];
            #pragma unroll
            for (int mt = 0; mt < 2; mt++) {
                int r = wm * 32 + mt * 16 + l7 + lb3 * 8;
                int c = k0 + lb4 * 8;
                ldsm_x4(ah[mt], (uint32_t)__cvta_generic_to_shared(Xh + r * WPAD + c));
                if (XF32)
                    ldsm_x4(al[mt], (uint32_t)__cvta_generic_to_shared(Xl + r * WPAD + c));
            }
            uint32_t bh[4][2], bl[4][2];
            #pragma unroll
            for (int p = 0; p < 2; p++) {
                int r = k0 + l7 + lb3 * 8;
                int c = wn * 32 + p * 16 + lb4 * 8;
                uint32_t t[4];
                ldsm_x4t(t, (uint32_t)__cvta_generic_to_shared(Wh + r * WPAD + c));
                bh[2*p][0] = t[0]; bh[2*p][1] = t[1]; bh[2*p+1][0] = t[2]; bh[2*p+1][1] = t[3];
                ldsm_x4t(t, (uint32_t)__cvta_generic_to_shared(Wl + r * WPAD + c));
                bl[2*p][0] = t[0]; bl[2*p][1] = t[1]; bl[2*p+1][0] = t[2]; bl[2*p+1][1] = t[3];
            }
            #pragma unroll
            for (int mt = 0; mt < 2; mt++)
                #pragma unroll
                for (int nt = 0; nt < 4; nt++) {
                    mma_bf16(acc[mt][nt], ah[mt], bh[nt]);
                    mma_bf16(acc[mt][nt], ah[mt], bl[nt]);
                    if (XF32)
                        mma_bf16(acc[mt][nt], al[mt], bh[nt]);
                }
        }

        #pragma unroll
        for (int mt = 0; mt < 2; mt++) {
            int r_lo = row0 + wm * 32 + mt * 16 + quad;
            int r_hi = r_lo + 8;
            float s_lo = (r_lo < n) ? dinv[r_lo] : 0.f;
            float s_hi = (r_hi < n) ? dinv[r_hi] : 0.f;
            #pragma unroll
            for (int nt = 0; nt < 4; nt++) {
                int c = wn * 32 + nt * 8 + tcol;
                if (r_lo < n) {
                    __nv_bfloat162 p = __floats2bfloat162_rn(acc[mt][nt][0] * s_lo,
                                                             acc[mt][nt][1] * s_lo);
                    *(uint32_t*)(out + (size_t)r_lo * D + c) = *(uint32_t*)&p;
                }
                if (r_hi < n) {
                    __nv_bfloat162 p = __floats2bfloat162_rn(acc[mt][nt][2] * s_hi,
                                                             acc[mt][nt][3] * s_hi);
                    *(uint32_t*)(out + (size_t)r_hi * D + c) = *(uint32_t*)&p;
                }
            }
        }
        __syncthreads();   // all ldsm reads done before next tile restages X
    }
}

// ---------------- fused CSR aggregate + post (bf16 h in/out) ----------------
__device__ __forceinline__ void acc_bf16x8_w(float* a, uint4 q, float w) {
    __nv_bfloat162 b0 = *(__nv_bfloat162*)&q.x;
    __nv_bfloat162 b1 = *(__nv_bfloat162*)&q.y;
    __nv_bfloat162 b2 = *(__nv_bfloat162*)&q.z;
    __nv_bfloat162 b3 = *(__nv_bfloat162*)&q.w;
    float2 f0 = __bfloat1622float2(b0);
    float2 f1 = __bfloat1622float2(b1);
    float2 f2 = __bfloat1622float2(b2);
    float2 f3 = __bfloat1622float2(b3);
    a[0] = fmaf(f0.x, w, a[0]); a[1] = fmaf(f0.y, w, a[1]);
    a[2] = fmaf(f1.x, w, a[2]); a[3] = fmaf(f1.y, w, a[3]);
    a[4] = fmaf(f2.x, w, a[4]); a[5] = fmaf(f2.y, w, a[5]);
    a[6] = fmaf(f3.x, w, a[6]); a[7] = fmaf(f3.y, w, a[7]);
}

__global__ void __launch_bounds__(256)
agg_post_kernel(const __nv_bfloat16* __restrict__ g,
                const int* __restrict__ csr_src, const int* __restrict__ row_start,
                const __nv_bfloat16* __restrict__ resid,
                const float* __restrict__ dinv,
                const float* __restrict__ bias,
                const float* __restrict__ gamma,
                const float* __restrict__ beta,
                __nv_bfloat16* __restrict__ h_out,
                const int* __restrict__ batch,
                float* __restrict__ pooled,
                int n, int do_relu, int do_pool) {
    int warp = (blockIdx.x * blockDim.x + threadIdx.x) >> 5;
    int lane = threadIdx.x & 31;
    if (warp >= n) return;

    int half = lane >> 4;
    int hl   = lane & 15;
    int colb = hl * 8;

    int beg = row_start[warp];
    int cnt = row_start[warp + 1] - beg;

    float acc[8];
    #pragma unroll
    for (int k = 0; k < 8; k++) acc[k] = 0.f;

    if (half == 0) {   // self-loop term
        uint4 q = *(const uint4*)(g + (size_t)warp * D + colb);
        acc_bf16x8_w(acc, q, 1.0f);
    }

    for (int base = 0; base < cnt; base += 32) {
        int m = min(32, cnt - base);
        // lanes past the end default to this warp's own (valid) row; masked by w=0
        int idx = (base + lane < cnt) ? __ldg(&csr_src[beg + base + lane]) : warp;
        for (int j = 0; j < m; j += 8) {
            uint4 v[4];
            float w[4];
            #pragma unroll
            for (int p = 0; p < 4; p++) {
                int k = j + 2 * p + half;
                int s = __shfl_sync(0xffffffffu, idx, k);  // k>=32 wraps to valid lane
                w[p] = (k < m) ? 1.0f : 0.0f;
                v[p] = *(const uint4*)(g + (size_t)s * D + colb);
            }
            #pragma unroll
            for (int p = 0; p < 4; p++) acc_bf16x8_w(acc, v[p], w[p]);
        }
    }

    #pragma unroll
    for (int k = 0; k < 8; k++)
        acc[k] += __shfl_xor_sync(0xffffffffu, acc[k], 16);

    float sc = dinv[warp];
    float t[8];
    {
        float4 b0 = *(const float4*)(bias + colb);
        float4 b1 = *(const float4*)(bias + colb + 4);
        t[0] = acc[0] * sc + b0.x; t[1] = acc[1] * sc + b0.y;
        t[2] = acc[2] * sc + b0.z; t[3] = acc[3] * sc + b0.w;
        t[4] = acc[4] * sc + b1.x; t[5] = acc[5] * sc + b1.y;
        t[6] = acc[6] * sc + b1.z; t[7] = acc[7] * sc + b1.w;
    }

    // single-pass LN: reduce sum and sumsq together (interleaved shfl chains)
    float sum = 0.f, ss = 0.f;
    #pragma unroll
    for (int k = 0; k < 8; k++) { sum += t[k]; ss = fmaf(t[k], t[k], ss); }
    #pragma unroll
    for (int o = 16; o > 0; o >>= 1) {
        sum += __shfl_xor_sync(0xffffffffu, sum, o);
        ss  += __shfl_xor_sync(0xffffffffu, ss, o);
    }
    float mu  = sum * (1.0f / (2 * D));
    float var = ss * (1.0f / (2 * D)) - mu * mu;
    float inv = rsqrtf(fmaxf(var, 0.0f) + LN_EPS);

    float y[8];
    {
        float4 g0 = *(const float4*)(gamma + colb);
        float4 g1 = *(const float4*)(gamma + colb + 4);
        float4 e0 = *(const float4*)(beta + colb);
        float4 e1 = *(const float4*)(beta + colb + 4);
        y[0] = (t[0] - mu) * inv * g0.x + e0.x; y[1] = (t[1] - mu) * inv * g0.y + e0.y;
        y[2] = (t[2] - mu) * inv * g0.z + e0.z; y[3] = (t[3] - mu) * inv * g0.w + e0.w;
        y[4] = (t[4] - mu) * inv * g1.x + e1.x; y[5] = (t[5] - mu) * inv * g1.y + e1.y;
        y[6] = (t[6] - mu) * inv * g1.z + e1.z; y[7] = (t[7] - mu) * inv * g1.w + e1.w;
    }

    if (resid) {
        uint4 r = *(const uint4*)(resid + (size_t)warp * D + colb);
        float racc[8] = {0, 0, 0, 0, 0, 0, 0, 0};
        acc_bf16x8_w(racc, r, 1.0f);
        #pragma unroll
        for (int k = 0; k < 8; k++) y[k] += racc[k];
    }
    if (do_relu) {
        #pragma unroll
        for (int k = 0; k < 8; k++) y[k] = fmaxf(y[k], 0.f);
    }

    if (half == 0) {
        if (do_pool) {
            int b = batch[warp];
            float* p = pooled + (size_t)b * D + colb;
            asm volatile("red.global.add.v4.f32 [%0], {%1,%2,%3,%4};"
                         :: "l"(p), "f"(y[0]), "f"(y[1]), "f"(y[2]), "f"(y[3]) : "memory");
            asm volatile("red.global.add.v4.f32 [%0], {%1,%2,%3,%4};"
                         :: "l"(p + 4), "f"(y[4]), "f"(y[5]), "f"(y[6]), "f"(y[7]) : "memory");
        } else {
            __nv_bfloat162 p0 = __floats2bfloat162_rn(y[0], y[1]);
            __nv_bfloat162 p1 = __floats2bfloat162_rn(y[2], y[3]);
            __nv_bfloat162 p2 = __floats2bfloat162_rn(y[4], y[5]);
            __nv_bfloat162 p3 = __floats2bfloat162_rn(y[6], y[7]);
            uint4 o;
            o.x = *(uint32_t*)&p0; o.y = *(uint32_t*)&p1;
            o.z = *(uint32_t*)&p2; o.w = *(uint32_t*)&p3;
            *(uint4*)(h_out + (size_t)warp * D + colb) = o;
        }
    }
}

// ---------------- final readout ----------------
__global__ void out_kernel(const float* __restrict__ pooled, const float* __restrict__ gcnt,
                           const float* __restrict__ lin_w, const float* __restrict__ lin_b,
                           float* __restrict__ out, int ngraphs) {
    int warp = (blockIdx.x * blockDim.x + threadIdx.x) >> 5;
    int lane = threadIdx.x & 31;
    if (warp >= ngraphs) return;
    float acc = 0.f;
    #pragma unroll
    for (int q = 0; q < 4; q++) {
        int j = lane + 32 * q;
        acc += pooled[(size_t)warp * D + j] * lin_w[j];
    }
    #pragma unroll
    for (int o = 16; o > 0; o >>= 1) acc += __shfl_xor_sync(0xffffffffu, acc, o);
    if (lane == 0)
        out[warp] = acc / fmaxf(gcnt[warp], 1.0f) + lin_b[0];
}

// ---------------- host launcher ----------------
extern "C" void kernel_launch(void* const* d_in, const int* in_sizes, int n_in,
                              void* d_out, int out_size) {
    const float* x      = (const float*)d_in[0];
    const void*  ei     = d_in[1];
    const void*  batch  = d_in[2];
    const float* Ws     = (const float*)d_in[3];
    const float* bs     = (const float*)d_in[4];
    const float* gammas = (const float*)d_in[5];
    const float* betas  = (const float*)d_in[6];
    const float* lin_w  = (const float*)d_in[7];
    const float* lin_b  = (const float*)d_in[8];
    float* out = (float*)d_out;

    int n = in_sizes[2];
    int E = in_sizes[1] / 2;
    int ngraphs = out_size;
    if (n > NMAX) n = NMAX;
    if (E > EMAX) E = EMAX;

    __nv_bfloat16 *bufG, *bufA, *bufB, *Whi, *Wlo;
    float *dinv, *pooled, *gcnt;
    int *csr_src, *cnt_int, *row_start, *wr_ptr, *blockSums, *batch32;
    cudaGetSymbolAddress((void**)&bufG,      d_bufG);
    cudaGetSymbolAddress((void**)&Whi,       d_Whi);
    cudaGetSymbolAddress((void**)&Wlo,       d_Wlo);
    cudaGetSymbolAddress((void**)&bufA,      d_bufA);
    cudaGetSymbolAddress((void**)&bufB,      d_bufB);
    cudaGetSymbolAddress((void**)&dinv,      d_dinv);
    cudaGetSymbolAddress((void**)&csr_src,   d_csr_src);
    cudaGetSymbolAddress((void**)&cnt_int,   d_cnt_int);
    cudaGetSymbolAddress((void**)&row_start, d_row_start);
    cudaGetSymbolAddress((void**)&wr_ptr,    d_wr_ptr);
    cudaGetSymbolAddress((void**)&blockSums, d_blockSums);
    cudaGetSymbolAddress((void**)&batch32,   d_batch32);
    cudaGetSymbolAddress((void**)&pooled,    d_pooled);
    cudaGetSymbolAddress((void**)&gcnt,      d_gcnt);

    const int smem_bytes = (2 * 128 * WPAD + 2 * 64 * WPAD) * sizeof(__nv_bfloat16);
    cudaFuncSetAttribute(gemm_kernel<true>, cudaFuncAttributeMaxDynamicSharedMemorySize, smem_bytes);
    cudaFuncSetAttribute(gemm_kernel<false>, cudaFuncAttributeMaxDynamicSharedMemorySize, smem_bytes);

    // ---- preamble ----
    detect_kernel<<<1, 32>>>((const int*)ei);
    cudaMemsetAsync(cnt_int, 0, (size_t)n * sizeof(int));
    cudaMemsetAsync(gcnt, 0, (size_t)ngraphs * sizeof(float));
    cudaMemsetAsync(pooled, 0, (size_t)ngraphs * D * sizeof(float));

    wsplit_kernel<<<(NLAYER * D * D + 255) / 256, 256>>>(Ws, Whi, Wlo);
    hist_kernel<<<(E + 255) / 256, 256>>>(ei, cnt_int, E, n);
    cvt_batch_kernel<<<(n + 255) / 256, 256>>>(batch, batch32, gcnt, n);

    int nb = (n + SCAN_BLOCK - 1) / SCAN_BLOCK;
    scanA_kernel<<<nb, SCAN_TPB>>>(cnt_int, row_start, blockSums, n);
    scanB_kernel<<<1, SCAN_MAXBLOCKS>>>(blockSums, nb);
    scanC_kernel<<<(n + 255) / 256, 256>>>(row_start, blockSums, wr_ptr, cnt_int, dinv, n, E);
    scatter_kernel<<<(E + 255) / 256, 256>>>(ei, wr_ptr, csr_src, E, n);

    // ---- layers ----
    int ntiles = (n + 63) / 64;
    int gemm_grid = (ntiles < GEMM_GRID) ? ntiles : GEMM_GRID;
    int row_warp_blocks = (n + 7) / 8;
    const void* in_ptr = x;
    __nv_bfloat16* hbufs[2] = {bufA, bufB};
    for (int l = 0; l < 4; l++) {
        if (l == 0)
            gemm_kernel<true><<<gemm_grid, 256, smem_bytes>>>(in_ptr, Whi, Wlo, dinv, bufG, n, ntiles);
        else
            gemm_kernel<false><<<gemm_grid, 256, smem_bytes>>>(in_ptr, Whi + (size_t)l * D * D,
                                                               Wlo + (size_t)l * D * D, dinv, bufG, n, ntiles);
        __nv_bfloat16* h_out = hbufs[l & 1];
        int do_pool = (l == 3);
        agg_post_kernel<<<row_warp_blocks, 256>>>(bufG, csr_src, row_start,
                                                  (l == 0) ? nullptr : (const __nv_bfloat16*)in_ptr,
                                                  dinv,
                                                  bs + l * D, gammas + l * D, betas + l * D,
                                                  h_out, batch32, pooled,
                                                  n, (l < 3) ? 1 : 0, do_pool);
        in_ptr = h_out;
    }

    out_kernel<<<(ngraphs * 32 + 255) / 256, 256>>>(pooled, gcnt, lin_w, lin_b, out, ngraphs);
}